// round 2
// baseline (speedup 1.0000x reference)
#include <cuda_runtime.h>
#include <cuda_bf16.h>
#include <cstddef>

#define NNODES 100000
#define C1 256   // hidden channels
#define C2 128   // fused mu|logvar channels

// Scratch (static device globals — allocation-free rule)
__device__ __align__(16) float g_deg [NNODES];
__device__ __align__(16) float g_dinv[NNODES];
__device__ __align__(16) float g_t1  [(size_t)NNODES * C1]; // dinv-scaled x@W1 (gather src)
__device__ __align__(16) float g_acc1[(size_t)NNODES * C1]; // accumulator (init = self loop), later h
__device__ __align__(16) float g_t2  [(size_t)NNODES * C2]; // dinv-scaled h@[Wmu|Wlv]
__device__ __align__(16) float g_acc2[(size_t)NNODES * C2];

// ---------------- degree / dinv ----------------
__global__ void init_deg(int M) {
    int i = blockIdx.x * blockDim.x + threadIdx.x;
    if (i < M) g_deg[i] = 1.0f;  // self loop
}
__global__ void count_deg(const int* __restrict__ ei, int E) {
    int e = blockIdx.x * blockDim.x + threadIdx.x;
    if (e < E) {
        int d = ei[(size_t)E + e];   // dst row
        atomicAdd(&g_deg[d], 1.0f);
    }
}
__global__ void compute_dinv(int M) {
    int i = blockIdx.x * blockDim.x + threadIdx.x;
    if (i < M) g_dinv[i] = rsqrtf(g_deg[i]);
}

// ---------------- tiled fp32 GEMM with dinv-scaled epilogue ----------------
// C_t[r, col_off+c] = C_acc[r, col_off+c] = dinv[r] * (A @ B)[r, c]
// BM=128, BN=64, BK=16, 256 threads, each thread 8x4 outputs.
#define GBM 128
#define GBN 64
#define GBK 16
__global__ __launch_bounds__(256) void gemm_scaled(
    const float* __restrict__ A, int lda,
    const float* __restrict__ B, int ldb,
    float* __restrict__ Ct, float* __restrict__ Cacc,
    int ldc, int col_off,
    const float* __restrict__ dinv, int M, int K)
{
    __shared__ float As[GBK][GBM + 4];
    __shared__ float Bs[GBK][GBN];

    const int tid = threadIdx.x;
    const int tx = tid & 15;   // col group (4 cols)
    const int ty = tid >> 4;   // row group (8 rows)
    const int row0 = blockIdx.x * GBM;
    const int bcol0 = blockIdx.y * GBN;

    float acc[8][4];
#pragma unroll
    for (int i = 0; i < 8; i++)
#pragma unroll
        for (int j = 0; j < 4; j++) acc[i][j] = 0.f;

    for (int k0 = 0; k0 < K; k0 += GBK) {
        // A tile: 128 x 16
#pragma unroll
        for (int j = 0; j < 8; j++) {
            int i = tid + j * 256;
            int m = i >> 4;
            int kk = i & 15;
            int r = row0 + m;
            As[kk][m] = (r < M) ? A[(size_t)r * lda + k0 + kk] : 0.f;
        }
        // B tile: 16 x 64
#pragma unroll
        for (int j = 0; j < 4; j++) {
            int i = tid + j * 256;
            int kk = i >> 6;
            int n = i & 63;
            Bs[kk][n] = B[(size_t)(k0 + kk) * ldb + bcol0 + n];
        }
        __syncthreads();
#pragma unroll
        for (int kk = 0; kk < GBK; kk++) {
            float a[8], b[4];
#pragma unroll
            for (int i = 0; i < 8; i++) a[i] = As[kk][ty * 8 + i];
#pragma unroll
            for (int j = 0; j < 4; j++) b[j] = Bs[kk][tx * 4 + j];
#pragma unroll
            for (int i = 0; i < 8; i++)
#pragma unroll
                for (int j = 0; j < 4; j++) acc[i][j] = fmaf(a[i], b[j], acc[i][j]);
        }
        __syncthreads();
    }

#pragma unroll
    for (int i = 0; i < 8; i++) {
        int r = row0 + ty * 8 + i;
        if (r >= M) continue;
        float dv = dinv[r];
#pragma unroll
        for (int j = 0; j < 4; j++) {
            int c = col_off + bcol0 + tx * 4 + j;
            float v = acc[i][j] * dv;
            Ct[(size_t)r * ldc + c] = v;
            Cacc[(size_t)r * ldc + c] = v;  // self-loop init
        }
    }
}

// ---------------- edge scatter: acc[dst] += t[src]  (one warp per edge) ----------------
template <int VPL>  // float4s per lane: 2 -> 256 ch, 1 -> 128 ch
__global__ __launch_bounds__(256) void scatter_add(
    const int* __restrict__ ei, int E,
    const float* __restrict__ t, float* __restrict__ acc, int C)
{
    int w = (blockIdx.x * blockDim.x + threadIdx.x) >> 5;
    if (w >= E) return;
    int lane = threadIdx.x & 31;
    int s = ei[w];
    int d = ei[(size_t)E + w];
    const float4* sp = (const float4*)(t + (size_t)s * C);
    float* dp = acc + (size_t)d * C;
#pragma unroll
    for (int v = 0; v < VPL; v++) {
        float4 x = sp[lane + v * 32];
        int c = (lane + v * 32) * 4;
        atomicAdd(dp + c + 0, x.x);
        atomicAdd(dp + c + 1, x.y);
        atomicAdd(dp + c + 2, x.z);
        atomicAdd(dp + c + 3, x.w);
    }
}

// ---------------- layer-1 finalize (in place): acc1 = relu(dinv*acc1 + b1) ----------------
__global__ void finalize_relu(const float* __restrict__ b1,
                              const float* __restrict__ dinv, int M)
{
    int idx = blockIdx.x * blockDim.x + threadIdx.x;  // over M * 64 float4s
    int total = M * (C1 / 4);
    if (idx >= total) return;
    int row = idx / (C1 / 4);
    int c4 = idx % (C1 / 4);
    float dv = dinv[row];
    float4 v = ((const float4*)g_acc1)[idx];
    float4 bb = ((const float4*)b1)[c4];
    float4 o;
    o.x = fmaxf(fmaf(dv, v.x, bb.x), 0.f);
    o.y = fmaxf(fmaf(dv, v.y, bb.y), 0.f);
    o.z = fmaxf(fmaf(dv, v.z, bb.z), 0.f);
    o.w = fmaxf(fmaf(dv, v.w, bb.w), 0.f);
    ((float4*)g_acc1)[idx] = o;
}

// ---------------- head: mu/logvar finalize + reparameterize + classifier ----------------
// out layout: [out | mu | logvar], each M x 64
__global__ __launch_bounds__(256) void head_kernel(
    const float* __restrict__ dinv,
    const float* __restrict__ b_mu, const float* __restrict__ b_lv,
    const float* __restrict__ W_c, const float* __restrict__ b_c,
    const float* __restrict__ eps,
    float* __restrict__ out, int M)
{
    __shared__ float Wc[64 * 64];
    __shared__ float zs[4][64];
    int tid = threadIdx.x;
    for (int i = tid; i < 64 * 64; i += 256) Wc[i] = W_c[i];

    int c = tid & 63;
    int sub = tid >> 6;
    int n = blockIdx.x * 4 + sub;
    size_t MO = (size_t)M * 64;

    if (n < M) {
        float dv = dinv[n];
        float mu = fmaf(dv, g_acc2[(size_t)n * C2 + c], b_mu[c]);
        float lv = fmaf(dv, g_acc2[(size_t)n * C2 + 64 + c], b_lv[c]);
        float z = fmaf(eps[(size_t)n * 64 + c], __expf(0.5f * lv), mu);
        out[MO + (size_t)n * 64 + c] = mu;
        out[2 * MO + (size_t)n * 64 + c] = lv;
        zs[sub][c] = z;
    }
    __syncthreads();
    if (n < M) {
        float s = b_c[c];
#pragma unroll
        for (int k = 0; k < 64; k++) s = fmaf(zs[sub][k], Wc[k * 64 + c], s);
        out[(size_t)n * 64 + c] = s;
    }
}

extern "C" void kernel_launch(void* const* d_in, const int* in_sizes, int n_in,
                              void* d_out, int out_size) {
    const float* x       = (const float*)d_in[0];
    const int*   ei      = (const int*)d_in[1];   // int32! (JAX x64-disabled downgrades int64)
    const float* W1      = (const float*)d_in[2];
    const float* b1      = (const float*)d_in[3];
    const float* W_mu    = (const float*)d_in[4];
    const float* b_mu    = (const float*)d_in[5];
    const float* W_lv    = (const float*)d_in[6];
    const float* b_lv    = (const float*)d_in[7];
    const float* W_c     = (const float*)d_in[8];
    const float* b_c     = (const float*)d_in[9];
    const float* eps     = (const float*)d_in[10];
    float* out = (float*)d_out;

    const int M = in_sizes[0] / 512;     // 100000
    const int E = in_sizes[1] / 2;       // 3200000

    float *dinv, *t1, *acc1, *t2, *acc2;
    cudaGetSymbolAddress((void**)&dinv, g_dinv);
    cudaGetSymbolAddress((void**)&t1,   g_t1);
    cudaGetSymbolAddress((void**)&acc1, g_acc1);
    cudaGetSymbolAddress((void**)&t2,   g_t2);
    cudaGetSymbolAddress((void**)&acc2, g_acc2);

    // 1) degree + dinv
    init_deg<<<(M + 255) / 256, 256>>>(M);
    count_deg<<<(E + 255) / 256, 256>>>(ei, E);
    compute_dinv<<<(M + 255) / 256, 256>>>(M);

    // 2) GEMM1: t1 = acc1 = dinv * (x @ W1)   [M x 256]
    {
        dim3 grid((M + GBM - 1) / GBM, C1 / GBN);
        gemm_scaled<<<grid, 256>>>(x, 512, W1, C1, t1, acc1, C1, 0, dinv, M, 512);
    }
    // 3) edge scatter layer 1 (256 ch)
    scatter_add<2><<<(E + 7) / 8, 256>>>(ei, E, t1, acc1, C1);
    // 4) finalize: h = relu(dinv*acc1 + b1), in place in acc1
    finalize_relu<<<(M * (C1 / 4) + 255) / 256, 256>>>(b1, dinv, M);

    // 5) fused head GEMMs: t2 = acc2 = dinv * (h @ [W_mu | W_lv])  [M x 128]
    {
        dim3 grid((M + GBM - 1) / GBM, 1);
        gemm_scaled<<<grid, 256>>>(acc1, C1, W_mu, 64, t2, acc2, C2, 0,  dinv, M, C1);
        gemm_scaled<<<grid, 256>>>(acc1, C1, W_lv, 64, t2, acc2, C2, 64, dinv, M, C1);
    }
    // 6) edge scatter layer 2 (128 ch)
    scatter_add<1><<<(E + 7) / 8, 256>>>(ei, E, t2, acc2, C2);

    // 7) mu/logvar + reparameterize + classifier
    head_kernel<<<(M + 3) / 4, 256>>>(dinv, b_mu, b_lv, W_c, b_c, eps, out, M);
}

// round 3
// speedup vs baseline: 2.9489x; 2.9489x over previous
#include <cuda_runtime.h>
#include <cuda_bf16.h>
#include <cstddef>

#define NNODES 100000
#define NEDGES 3200000
#define C1 256
#define C2 128
#define SCAN_B 1024
#define NBLK ((NNODES + SCAN_B - 1) / SCAN_B)   // 98

// ---- scratch (static device globals) ----
__device__ int g_cnt   [NNODES];       // in-degree (no self loop)
__device__ int g_rowptr[NNODES];       // CSR row start
__device__ int g_cursor[NNODES];       // fill cursor
__device__ int g_bsum  [NBLK];
__device__ int g_boff  [NBLK];
__device__ int g_srclist[NEDGES];
__device__ __align__(16) float g_dinv[NNODES];
__device__ __align__(16) float g_t1 [(size_t)NNODES * C1];  // dinv * (x@W1)
__device__ __align__(16) float g_h  [(size_t)NNODES * C1];  // relu-ed hidden
__device__ __align__(16) float g_t2 [(size_t)NNODES * C2];  // dinv * (h@[Wmu|Wlv])
__device__ __align__(16) float g_acc2[(size_t)NNODES * C2]; // raw aggregated sums

// ---------------- CSR build ----------------
__global__ void zero_cnt(int M) {
    int i = blockIdx.x * blockDim.x + threadIdx.x;
    if (i < M) g_cnt[i] = 0;
}
__global__ void count_deg(const int* __restrict__ ei, int E) {
    int e = blockIdx.x * blockDim.x + threadIdx.x;
    if (e < E) atomicAdd(&g_cnt[ei[(size_t)E + e]], 1);
}
__global__ void compute_dinv(int M) {
    int i = blockIdx.x * blockDim.x + threadIdx.x;
    if (i < M) g_dinv[i] = rsqrtf((float)(g_cnt[i] + 1));
}
// local exclusive scan per 1024-block
__global__ __launch_bounds__(SCAN_B) void scan_local(int M) {
    __shared__ int sh[SCAN_B];
    int tid = threadIdx.x;
    int i = blockIdx.x * SCAN_B + tid;
    int v = (i < M) ? g_cnt[i] : 0;
    sh[tid] = v;
    __syncthreads();
#pragma unroll
    for (int off = 1; off < SCAN_B; off <<= 1) {
        int t = (tid >= off) ? sh[tid - off] : 0;
        __syncthreads();
        sh[tid] += t;
        __syncthreads();
    }
    if (i < M) g_rowptr[i] = sh[tid] - v;   // exclusive (local)
    if (tid == SCAN_B - 1) g_bsum[blockIdx.x] = sh[tid];
}
__global__ void scan_bsums() {
    if (threadIdx.x == 0) {
        int acc = 0;
        for (int b = 0; b < NBLK; b++) { g_boff[b] = acc; acc += g_bsum[b]; }
    }
}
__global__ void scan_apply(int M) {
    int i = blockIdx.x * blockDim.x + threadIdx.x;
    if (i < M) {
        int r = g_rowptr[i] + g_boff[i / SCAN_B];
        g_rowptr[i] = r;
        g_cursor[i] = r;
    }
}
__global__ void fill_csr(const int* __restrict__ ei, int E) {
    int e = blockIdx.x * blockDim.x + threadIdx.x;
    if (e < E) {
        int s = ei[e];
        int d = ei[(size_t)E + e];
        int pos = atomicAdd(&g_cursor[d], 1);
        g_srclist[pos] = s;
    }
}

// ---------------- tiled fp32 GEMM with dinv-scaled epilogue ----------------
#define GBM 128
#define GBN 64
#define GBK 16
__global__ __launch_bounds__(256) void gemm_scaled(
    const float* __restrict__ A, int lda,
    const float* __restrict__ B, int ldb,
    float* __restrict__ Ct, int ldc, int col_off,
    const float* __restrict__ dinv, int M, int K)
{
    __shared__ float As[GBK][GBM + 4];
    __shared__ float Bs[GBK][GBN];

    const int tid = threadIdx.x;
    const int tx = tid & 15;
    const int ty = tid >> 4;
    const int row0 = blockIdx.x * GBM;
    const int bcol0 = blockIdx.y * GBN;

    float acc[8][4];
#pragma unroll
    for (int i = 0; i < 8; i++)
#pragma unroll
        for (int j = 0; j < 4; j++) acc[i][j] = 0.f;

    for (int k0 = 0; k0 < K; k0 += GBK) {
#pragma unroll
        for (int j = 0; j < 8; j++) {
            int i = tid + j * 256;
            int m = i >> 4;
            int kk = i & 15;
            int r = row0 + m;
            As[kk][m] = (r < M) ? A[(size_t)r * lda + k0 + kk] : 0.f;
        }
#pragma unroll
        for (int j = 0; j < 4; j++) {
            int i = tid + j * 256;
            int kk = i >> 6;
            int n = i & 63;
            Bs[kk][n] = B[(size_t)(k0 + kk) * ldb + bcol0 + n];
        }
        __syncthreads();
#pragma unroll
        for (int kk = 0; kk < GBK; kk++) {
            float a[8], b[4];
#pragma unroll
            for (int i = 0; i < 8; i++) a[i] = As[kk][ty * 8 + i];
#pragma unroll
            for (int j = 0; j < 4; j++) b[j] = Bs[kk][tx * 4 + j];
#pragma unroll
            for (int i = 0; i < 8; i++)
#pragma unroll
                for (int j = 0; j < 4; j++) acc[i][j] = fmaf(a[i], b[j], acc[i][j]);
        }
        __syncthreads();
    }

#pragma unroll
    for (int i = 0; i < 8; i++) {
        int r = row0 + ty * 8 + i;
        if (r >= M) continue;
        float dv = dinv[r];
#pragma unroll
        for (int j = 0; j < 4; j++) {
            int c = col_off + bcol0 + tx * 4 + j;
            Ct[(size_t)r * ldc + c] = acc[i][j] * dv;
        }
    }
}

__device__ __forceinline__ void f4add(float4& a, const float4 b) {
    a.x += b.x; a.y += b.y; a.z += b.z; a.w += b.w;
}

// ---------------- gather layer 1: h = relu(dinv*(self + sum_src t1[src]) + b1) ----------------
__global__ __launch_bounds__(256) void gather1(const float* __restrict__ b1, int M)
{
    int w = (blockIdx.x * blockDim.x + threadIdx.x) >> 5;
    if (w >= M) return;
    int lane = threadIdx.x & 31;
    int base = g_rowptr[w];
    int deg = g_cnt[w];

    const float4* selfp = (const float4*)(g_t1 + (size_t)w * C1);
    float4 a0 = selfp[lane];
    float4 a1 = selfp[lane + 32];

    for (int j = 0; j < deg; j += 32) {
        int nrem = min(32, deg - j);
        int idx = (j + lane < deg) ? g_srclist[base + j + lane] : 0;
        // process two edges per step for MLP
        int k = 0;
        for (; k + 1 < nrem; k += 2) {
            int s0 = __shfl_sync(0xffffffff, idx, k);
            int s1 = __shfl_sync(0xffffffff, idx, k + 1);
            const float4* p0 = (const float4*)(g_t1 + (size_t)s0 * C1);
            const float4* p1 = (const float4*)(g_t1 + (size_t)s1 * C1);
            float4 x0 = p0[lane], x1 = p0[lane + 32];
            float4 y0 = p1[lane], y1 = p1[lane + 32];
            f4add(a0, x0); f4add(a1, x1);
            f4add(a0, y0); f4add(a1, y1);
        }
        if (k < nrem) {
            int s0 = __shfl_sync(0xffffffff, idx, k);
            const float4* p0 = (const float4*)(g_t1 + (size_t)s0 * C1);
            f4add(a0, p0[lane]); f4add(a1, p0[lane + 32]);
        }
    }

    float dv = g_dinv[w];
    float4 bb0 = ((const float4*)b1)[lane];
    float4 bb1 = ((const float4*)b1)[lane + 32];
    float4 o0, o1;
    o0.x = fmaxf(fmaf(dv, a0.x, bb0.x), 0.f);
    o0.y = fmaxf(fmaf(dv, a0.y, bb0.y), 0.f);
    o0.z = fmaxf(fmaf(dv, a0.z, bb0.z), 0.f);
    o0.w = fmaxf(fmaf(dv, a0.w, bb0.w), 0.f);
    o1.x = fmaxf(fmaf(dv, a1.x, bb1.x), 0.f);
    o1.y = fmaxf(fmaf(dv, a1.y, bb1.y), 0.f);
    o1.z = fmaxf(fmaf(dv, a1.z, bb1.z), 0.f);
    o1.w = fmaxf(fmaf(dv, a1.w, bb1.w), 0.f);
    float4* hp = (float4*)(g_h + (size_t)w * C1);
    hp[lane] = o0;
    hp[lane + 32] = o1;
}

// ---------------- gather layer 2: acc2 = self + sum t2[src]   (raw, 128 ch) ----------------
__global__ __launch_bounds__(256) void gather2(int M)
{
    int w = (blockIdx.x * blockDim.x + threadIdx.x) >> 5;
    if (w >= M) return;
    int lane = threadIdx.x & 31;
    int base = g_rowptr[w];
    int deg = g_cnt[w];

    const float4* selfp = (const float4*)(g_t2 + (size_t)w * C2);
    float4 a0 = selfp[lane];

    for (int j = 0; j < deg; j += 32) {
        int nrem = min(32, deg - j);
        int idx = (j + lane < deg) ? g_srclist[base + j + lane] : 0;
        int k = 0;
        for (; k + 3 < nrem; k += 4) {
            int s0 = __shfl_sync(0xffffffff, idx, k);
            int s1 = __shfl_sync(0xffffffff, idx, k + 1);
            int s2 = __shfl_sync(0xffffffff, idx, k + 2);
            int s3 = __shfl_sync(0xffffffff, idx, k + 3);
            float4 x0 = ((const float4*)(g_t2 + (size_t)s0 * C2))[lane];
            float4 x1 = ((const float4*)(g_t2 + (size_t)s1 * C2))[lane];
            float4 x2 = ((const float4*)(g_t2 + (size_t)s2 * C2))[lane];
            float4 x3 = ((const float4*)(g_t2 + (size_t)s3 * C2))[lane];
            f4add(a0, x0); f4add(a0, x1); f4add(a0, x2); f4add(a0, x3);
        }
        for (; k < nrem; k++) {
            int s0 = __shfl_sync(0xffffffff, idx, k);
            f4add(a0, ((const float4*)(g_t2 + (size_t)s0 * C2))[lane]);
        }
    }
    ((float4*)(g_acc2 + (size_t)w * C2))[lane] = a0;
}

// ---------------- head: finalize mu/lv + reparameterize + classifier ----------------
__global__ __launch_bounds__(256) void head_kernel(
    const float* __restrict__ b_mu, const float* __restrict__ b_lv,
    const float* __restrict__ W_c, const float* __restrict__ b_c,
    const float* __restrict__ eps,
    float* __restrict__ out, int M)
{
    __shared__ float Wc[64 * 64];
    __shared__ float zs[4][64];
    int tid = threadIdx.x;
    for (int i = tid; i < 64 * 64; i += 256) Wc[i] = W_c[i];

    int c = tid & 63;
    int sub = tid >> 6;
    int n = blockIdx.x * 4 + sub;
    size_t MO = (size_t)M * 64;

    if (n < M) {
        float dv = g_dinv[n];
        float mu = fmaf(dv, g_acc2[(size_t)n * C2 + c], b_mu[c]);
        float lv = fmaf(dv, g_acc2[(size_t)n * C2 + 64 + c], b_lv[c]);
        float z = fmaf(eps[(size_t)n * 64 + c], __expf(0.5f * lv), mu);
        out[MO + (size_t)n * 64 + c] = mu;
        out[2 * MO + (size_t)n * 64 + c] = lv;
        zs[sub][c] = z;
    }
    __syncthreads();
    if (n < M) {
        float s = b_c[c];
#pragma unroll
        for (int k = 0; k < 64; k++) s = fmaf(zs[sub][k], Wc[k * 64 + c], s);
        out[(size_t)n * 64 + c] = s;
    }
}

extern "C" void kernel_launch(void* const* d_in, const int* in_sizes, int n_in,
                              void* d_out, int out_size) {
    const float* x    = (const float*)d_in[0];
    const int*   ei   = (const int*)d_in[1];    // int32
    const float* W1   = (const float*)d_in[2];
    const float* b1   = (const float*)d_in[3];
    const float* W_mu = (const float*)d_in[4];
    const float* b_mu = (const float*)d_in[5];
    const float* W_lv = (const float*)d_in[6];
    const float* b_lv = (const float*)d_in[7];
    const float* W_c  = (const float*)d_in[8];
    const float* b_c  = (const float*)d_in[9];
    const float* eps  = (const float*)d_in[10];
    float* out = (float*)d_out;

    const int M = in_sizes[0] / 512;   // 100000
    const int E = in_sizes[1] / 2;     // 3200000

    float *dinv, *t1, *h, *t2;
    cudaGetSymbolAddress((void**)&dinv, g_dinv);
    cudaGetSymbolAddress((void**)&t1,   g_t1);
    cudaGetSymbolAddress((void**)&h,    g_h);
    cudaGetSymbolAddress((void**)&t2,   g_t2);

    // ---- CSR build + dinv ----
    zero_cnt<<<(M + 255) / 256, 256>>>(M);
    count_deg<<<(E + 511) / 512, 512>>>(ei, E);
    compute_dinv<<<(M + 255) / 256, 256>>>(M);
    scan_local<<<NBLK, SCAN_B>>>(M);
    scan_bsums<<<1, 32>>>();
    scan_apply<<<(M + 255) / 256, 256>>>(M);
    fill_csr<<<(E + 511) / 512, 512>>>(ei, E);

    // ---- layer 1 ----
    {
        dim3 grid((M + GBM - 1) / GBM, C1 / GBN);
        gemm_scaled<<<grid, 256>>>(x, 512, W1, C1, t1, C1, 0, dinv, M, 512);
    }
    gather1<<<(M * 32 + 255) / 256, 256>>>(b1, M);

    // ---- layer 2 (fused mu|logvar) ----
    {
        dim3 grid((M + GBM - 1) / GBM, 1);
        gemm_scaled<<<grid, 256>>>(h, C1, W_mu, 64, t2, C2, 0,  dinv, M, C1);
        gemm_scaled<<<grid, 256>>>(h, C1, W_lv, 64, t2, C2, 64, dinv, M, C1);
    }
    gather2<<<(M * 32 + 255) / 256, 256>>>(M);

    // ---- head ----
    head_kernel<<<(M + 3) / 4, 256>>>(b_mu, b_lv, W_c, b_c, eps, out, M);
}

// round 4
// speedup vs baseline: 4.6552x; 1.5786x over previous
#include <cuda_runtime.h>
#include <cuda_bf16.h>
#include <cstddef>
#include <cstdint>

#define NNODES 100000
#define NEDGES 3200000
#define C1 256
#define C2 128
#define SCAN_B 1024
#define NBLK ((NNODES + SCAN_B - 1) / SCAN_B)   // 98

// ---- scratch (static device globals) ----
__device__ int g_cnt   [NNODES];
__device__ int g_rowptr[NNODES];
__device__ int g_cursor[NNODES];
__device__ int g_bsum  [NBLK];
__device__ int g_boff  [NBLK];
__device__ int g_srclist[NEDGES];
__device__ __align__(16) float g_dinv[NNODES];
__device__ __align__(16) float g_t1 [(size_t)NNODES * C1];
__device__ __align__(16) float g_h  [(size_t)NNODES * C1];
__device__ __align__(16) float g_t2 [(size_t)NNODES * C2];
__device__ __align__(16) float g_acc2[(size_t)NNODES * C2];

// ---------------- CSR build ----------------
__global__ void zero_cnt(int M) {
    int i = blockIdx.x * blockDim.x + threadIdx.x;
    if (i < M) g_cnt[i] = 0;
}
__global__ void count_deg(const int* __restrict__ ei, int E) {
    int e = blockIdx.x * blockDim.x + threadIdx.x;
    if (e < E) atomicAdd(&g_cnt[ei[(size_t)E + e]], 1);
}
__global__ void compute_dinv(int M) {
    int i = blockIdx.x * blockDim.x + threadIdx.x;
    if (i < M) g_dinv[i] = rsqrtf((float)(g_cnt[i] + 1));
}
__global__ __launch_bounds__(SCAN_B) void scan_local(int M) {
    __shared__ int sh[SCAN_B];
    int tid = threadIdx.x;
    int i = blockIdx.x * SCAN_B + tid;
    int v = (i < M) ? g_cnt[i] : 0;
    sh[tid] = v;
    __syncthreads();
#pragma unroll
    for (int off = 1; off < SCAN_B; off <<= 1) {
        int t = (tid >= off) ? sh[tid - off] : 0;
        __syncthreads();
        sh[tid] += t;
        __syncthreads();
    }
    if (i < M) g_rowptr[i] = sh[tid] - v;
    if (tid == SCAN_B - 1) g_bsum[blockIdx.x] = sh[tid];
}
__global__ void scan_bsums() {
    if (threadIdx.x == 0) {
        int acc = 0;
        for (int b = 0; b < NBLK; b++) { g_boff[b] = acc; acc += g_bsum[b]; }
    }
}
__global__ void scan_apply(int M) {
    int i = blockIdx.x * blockDim.x + threadIdx.x;
    if (i < M) {
        int r = g_rowptr[i] + g_boff[i / SCAN_B];
        g_rowptr[i] = r;
        g_cursor[i] = r;
    }
}
__global__ void fill_csr(const int* __restrict__ ei, int E) {
    int e = blockIdx.x * blockDim.x + threadIdx.x;
    if (e < E) {
        int s = ei[e];
        int d = ei[(size_t)E + e];
        int pos = atomicAdd(&g_cursor[d], 1);
        g_srclist[pos] = s;
    }
}

// ---------------- TF32 tensor-core GEMM, dinv-scaled epilogue ----------------
// Ct[r, col_off+c] = dinv[r] * (A @ B)[r, c]
#define TBM 128
#define TBN 64
#define TBK 32
#define AS_STRIDE (TBK + 4)   // 36: fragment reads hit 32 distinct banks
#define BS_STRIDE (TBN + 8)   // 72: q-rows shift by 8 banks -> conflict free

__device__ __forceinline__ float to_tf32(float v) {
    uint32_t u;
    asm("cvt.rna.tf32.f32 %0, %1;" : "=r"(u) : "f"(v));
    return __uint_as_float(u);
}

__global__ __launch_bounds__(256) void gemm_tf32(
    const float* __restrict__ A, int lda,
    const float* __restrict__ B, int ldb,
    float* __restrict__ Ct, int ldc, int col_off,
    const float* __restrict__ dinv, int M, int K)
{
    __shared__ float As[TBM][AS_STRIDE];
    __shared__ float Bs[TBK][BS_STRIDE];

    const int tid = threadIdx.x;
    const int lane = tid & 31;
    const int warp = tid >> 5;
    const int wm = warp & 3;           // 4 warps along M (32 rows each)
    const int wn = warp >> 2;          // 2 warps along N (32 cols each)
    const int gid = lane >> 2;
    const int q = lane & 3;
    const int row0 = blockIdx.x * TBM;
    const int bcol0 = blockIdx.y * TBN;

    float c[2][4][4];
#pragma unroll
    for (int mt = 0; mt < 2; mt++)
#pragma unroll
        for (int nt = 0; nt < 4; nt++)
#pragma unroll
            for (int r = 0; r < 4; r++) c[mt][nt][r] = 0.f;

    for (int k0 = 0; k0 < K; k0 += TBK) {
        // A tile 128x32, float4 x4 per thread
#pragma unroll
        for (int i = 0; i < 4; i++) {
            int idx = tid + i * 256;
            int r = idx >> 3;
            int c4 = (idx & 7) << 2;
            int gr = row0 + r;
            float4 v = (gr < M) ? *(const float4*)(A + (size_t)gr * lda + k0 + c4)
                                : make_float4(0.f, 0.f, 0.f, 0.f);
            As[r][c4 + 0] = to_tf32(v.x);
            As[r][c4 + 1] = to_tf32(v.y);
            As[r][c4 + 2] = to_tf32(v.z);
            As[r][c4 + 3] = to_tf32(v.w);
        }
        // B tile 32x64, float4 x2 per thread
#pragma unroll
        for (int i = 0; i < 2; i++) {
            int idx = tid + i * 256;
            int r = idx >> 4;
            int c4 = (idx & 15) << 2;
            float4 v = *(const float4*)(B + (size_t)(k0 + r) * ldb + bcol0 + c4);
            Bs[r][c4 + 0] = to_tf32(v.x);
            Bs[r][c4 + 1] = to_tf32(v.y);
            Bs[r][c4 + 2] = to_tf32(v.z);
            Bs[r][c4 + 3] = to_tf32(v.w);
        }
        __syncthreads();

#pragma unroll
        for (int ks = 0; ks < TBK / 8; ks++) {
            int kb = ks * 8;
            uint32_t a[2][4], b[4][2];
#pragma unroll
            for (int mt = 0; mt < 2; mt++) {
                int r = wm * 32 + mt * 16;
                a[mt][0] = __float_as_uint(As[r + gid][kb + q]);
                a[mt][1] = __float_as_uint(As[r + gid + 8][kb + q]);
                a[mt][2] = __float_as_uint(As[r + gid][kb + q + 4]);
                a[mt][3] = __float_as_uint(As[r + gid + 8][kb + q + 4]);
            }
#pragma unroll
            for (int nt = 0; nt < 4; nt++) {
                int cc = wn * 32 + nt * 8 + gid;
                b[nt][0] = __float_as_uint(Bs[kb + q][cc]);
                b[nt][1] = __float_as_uint(Bs[kb + q + 4][cc]);
            }
#pragma unroll
            for (int mt = 0; mt < 2; mt++)
#pragma unroll
                for (int nt = 0; nt < 4; nt++)
                    asm volatile(
                        "mma.sync.aligned.m16n8k8.row.col.f32.tf32.tf32.f32 "
                        "{%0,%1,%2,%3}, {%4,%5,%6,%7}, {%8,%9}, {%0,%1,%2,%3};"
                        : "+f"(c[mt][nt][0]), "+f"(c[mt][nt][1]),
                          "+f"(c[mt][nt][2]), "+f"(c[mt][nt][3])
                        : "r"(a[mt][0]), "r"(a[mt][1]), "r"(a[mt][2]), "r"(a[mt][3]),
                          "r"(b[nt][0]), "r"(b[nt][1]));
        }
        __syncthreads();
    }

    // epilogue: scale by dinv[row], float2 stores
#pragma unroll
    for (int mt = 0; mt < 2; mt++) {
        int r0 = row0 + wm * 32 + mt * 16 + gid;
        int r1 = r0 + 8;
        float dv0 = (r0 < M) ? dinv[r0] : 0.f;
        float dv1 = (r1 < M) ? dinv[r1] : 0.f;
#pragma unroll
        for (int nt = 0; nt < 4; nt++) {
            int cc = col_off + bcol0 + wn * 32 + nt * 8 + 2 * q;
            if (r0 < M) {
                float2 v = make_float2(c[mt][nt][0] * dv0, c[mt][nt][1] * dv0);
                *(float2*)(Ct + (size_t)r0 * ldc + cc) = v;
            }
            if (r1 < M) {
                float2 v = make_float2(c[mt][nt][2] * dv1, c[mt][nt][3] * dv1);
                *(float2*)(Ct + (size_t)r1 * ldc + cc) = v;
            }
        }
    }
}

__device__ __forceinline__ void f4add(float4& a, const float4 b) {
    a.x += b.x; a.y += b.y; a.z += b.z; a.w += b.w;
}

// ---------------- gather layer 1: h = relu(dinv*(self + sum_src t1[src]) + b1) ----------------
__global__ __launch_bounds__(256) void gather1(const float* __restrict__ b1, int M)
{
    int w = (blockIdx.x * blockDim.x + threadIdx.x) >> 5;
    if (w >= M) return;
    int lane = threadIdx.x & 31;
    int base = g_rowptr[w];
    int deg = g_cnt[w];

    const float4* selfp = (const float4*)(g_t1 + (size_t)w * C1);
    float4 a0 = selfp[lane];
    float4 a1 = selfp[lane + 32];

    for (int j = 0; j < deg; j += 32) {
        int nrem = min(32, deg - j);
        int idx = (j + lane < deg) ? g_srclist[base + j + lane] : 0;
        int k = 0;
        for (; k + 1 < nrem; k += 2) {
            int s0 = __shfl_sync(0xffffffff, idx, k);
            int s1 = __shfl_sync(0xffffffff, idx, k + 1);
            const float4* p0 = (const float4*)(g_t1 + (size_t)s0 * C1);
            const float4* p1 = (const float4*)(g_t1 + (size_t)s1 * C1);
            float4 x0 = p0[lane], x1 = p0[lane + 32];
            float4 y0 = p1[lane], y1 = p1[lane + 32];
            f4add(a0, x0); f4add(a1, x1);
            f4add(a0, y0); f4add(a1, y1);
        }
        if (k < nrem) {
            int s0 = __shfl_sync(0xffffffff, idx, k);
            const float4* p0 = (const float4*)(g_t1 + (size_t)s0 * C1);
            f4add(a0, p0[lane]); f4add(a1, p0[lane + 32]);
        }
    }

    float dv = g_dinv[w];
    float4 bb0 = ((const float4*)b1)[lane];
    float4 bb1 = ((const float4*)b1)[lane + 32];
    float4 o0, o1;
    o0.x = fmaxf(fmaf(dv, a0.x, bb0.x), 0.f);
    o0.y = fmaxf(fmaf(dv, a0.y, bb0.y), 0.f);
    o0.z = fmaxf(fmaf(dv, a0.z, bb0.z), 0.f);
    o0.w = fmaxf(fmaf(dv, a0.w, bb0.w), 0.f);
    o1.x = fmaxf(fmaf(dv, a1.x, bb1.x), 0.f);
    o1.y = fmaxf(fmaf(dv, a1.y, bb1.y), 0.f);
    o1.z = fmaxf(fmaf(dv, a1.z, bb1.z), 0.f);
    o1.w = fmaxf(fmaf(dv, a1.w, bb1.w), 0.f);
    float4* hp = (float4*)(g_h + (size_t)w * C1);
    hp[lane] = o0;
    hp[lane + 32] = o1;
}

// ---------------- gather layer 2: acc2 = self + sum t2[src] ----------------
__global__ __launch_bounds__(256) void gather2(int M)
{
    int w = (blockIdx.x * blockDim.x + threadIdx.x) >> 5;
    if (w >= M) return;
    int lane = threadIdx.x & 31;
    int base = g_rowptr[w];
    int deg = g_cnt[w];

    const float4* selfp = (const float4*)(g_t2 + (size_t)w * C2);
    float4 a0 = selfp[lane];

    for (int j = 0; j < deg; j += 32) {
        int nrem = min(32, deg - j);
        int idx = (j + lane < deg) ? g_srclist[base + j + lane] : 0;
        int k = 0;
        for (; k + 3 < nrem; k += 4) {
            int s0 = __shfl_sync(0xffffffff, idx, k);
            int s1 = __shfl_sync(0xffffffff, idx, k + 1);
            int s2 = __shfl_sync(0xffffffff, idx, k + 2);
            int s3 = __shfl_sync(0xffffffff, idx, k + 3);
            float4 x0 = ((const float4*)(g_t2 + (size_t)s0 * C2))[lane];
            float4 x1 = ((const float4*)(g_t2 + (size_t)s1 * C2))[lane];
            float4 x2 = ((const float4*)(g_t2 + (size_t)s2 * C2))[lane];
            float4 x3 = ((const float4*)(g_t2 + (size_t)s3 * C2))[lane];
            f4add(a0, x0); f4add(a0, x1); f4add(a0, x2); f4add(a0, x3);
        }
        for (; k < nrem; k++) {
            int s0 = __shfl_sync(0xffffffff, idx, k);
            f4add(a0, ((const float4*)(g_t2 + (size_t)s0 * C2))[lane]);
        }
    }
    ((float4*)(g_acc2 + (size_t)w * C2))[lane] = a0;
}

// ---------------- head: mu/lv finalize + reparameterize + classifier ----------------
__global__ __launch_bounds__(256) void head_kernel(
    const float* __restrict__ b_mu, const float* __restrict__ b_lv,
    const float* __restrict__ W_c, const float* __restrict__ b_c,
    const float* __restrict__ eps,
    float* __restrict__ out, int M)
{
    __shared__ float Wc[64 * 64];
    __shared__ float zs[4][64];
    int tid = threadIdx.x;
    for (int i = tid; i < 64 * 64; i += 256) Wc[i] = W_c[i];

    int c = tid & 63;
    int sub = tid >> 6;
    int n = blockIdx.x * 4 + sub;
    size_t MO = (size_t)M * 64;

    if (n < M) {
        float dv = g_dinv[n];
        float mu = fmaf(dv, g_acc2[(size_t)n * C2 + c], b_mu[c]);
        float lv = fmaf(dv, g_acc2[(size_t)n * C2 + 64 + c], b_lv[c]);
        float z = fmaf(eps[(size_t)n * 64 + c], __expf(0.5f * lv), mu);
        out[MO + (size_t)n * 64 + c] = mu;
        out[2 * MO + (size_t)n * 64 + c] = lv;
        zs[sub][c] = z;
    }
    __syncthreads();
    if (n < M) {
        float s = b_c[c];
#pragma unroll
        for (int k = 0; k < 64; k++) s = fmaf(zs[sub][k], Wc[k * 64 + c], s);
        out[(size_t)n * 64 + c] = s;
    }
}

extern "C" void kernel_launch(void* const* d_in, const int* in_sizes, int n_in,
                              void* d_out, int out_size) {
    const float* x    = (const float*)d_in[0];
    const int*   ei   = (const int*)d_in[1];
    const float* W1   = (const float*)d_in[2];
    const float* b1   = (const float*)d_in[3];
    const float* W_mu = (const float*)d_in[4];
    const float* b_mu = (const float*)d_in[5];
    const float* W_lv = (const float*)d_in[6];
    const float* b_lv = (const float*)d_in[7];
    const float* W_c  = (const float*)d_in[8];
    const float* b_c  = (const float*)d_in[9];
    const float* eps  = (const float*)d_in[10];
    float* out = (float*)d_out;

    const int M = in_sizes[0] / 512;   // 100000
    const int E = in_sizes[1] / 2;     // 3200000

    float *dinv, *t1, *h, *t2;
    cudaGetSymbolAddress((void**)&dinv, g_dinv);
    cudaGetSymbolAddress((void**)&t1,   g_t1);
    cudaGetSymbolAddress((void**)&h,    g_h);
    cudaGetSymbolAddress((void**)&t2,   g_t2);

    // ---- CSR build + dinv ----
    zero_cnt<<<(M + 255) / 256, 256>>>(M);
    count_deg<<<(E + 511) / 512, 512>>>(ei, E);
    compute_dinv<<<(M + 255) / 256, 256>>>(M);
    scan_local<<<NBLK, SCAN_B>>>(M);
    scan_bsums<<<1, 32>>>();
    scan_apply<<<(M + 255) / 256, 256>>>(M);
    fill_csr<<<(E + 511) / 512, 512>>>(ei, E);

    // ---- layer 1 ----
    {
        dim3 grid((M + TBM - 1) / TBM, C1 / TBN);
        gemm_tf32<<<grid, 256>>>(x, 512, W1, C1, t1, C1, 0, dinv, M, 512);
    }
    gather1<<<(M * 32 + 255) / 256, 256>>>(b1, M);

    // ---- layer 2 (fused mu|logvar) ----
    {
        dim3 grid((M + TBM - 1) / TBM, 1);
        gemm_tf32<<<grid, 256>>>(h, C1, W_mu, 64, t2, C2, 0,  dinv, M, C1);
        gemm_tf32<<<grid, 256>>>(h, C1, W_lv, 64, t2, C2, 64, dinv, M, C1);
    }
    gather2<<<(M * 32 + 255) / 256, 256>>>(M);

    // ---- head ----
    head_kernel<<<(M + 3) / 4, 256>>>(b_mu, b_lv, W_c, b_c, eps, out, M);
}

// round 5
// speedup vs baseline: 5.2782x; 1.1338x over previous
#include <cuda_runtime.h>
#include <cuda_fp16.h>
#include <cstddef>
#include <cstdint>

#define NNODES 100000
#define NEDGES 3200000
#define C1 256
#define C2 128
#define SCAN_B 1024
#define NBLK ((NNODES + SCAN_B - 1) / SCAN_B)   // 98

// ---- scratch (static device globals) ----
__device__ int g_cnt   [NNODES];
__device__ int g_rowptr[NNODES];
__device__ int g_cursor[NNODES];
__device__ int g_bsum  [NBLK];
__device__ int g_boff  [NBLK];
__device__ int g_srclist[NEDGES];
__device__ __align__(16) float  g_dinv[NNODES];
__device__ __align__(16) __half g_t1h[(size_t)NNODES * C1];  // fp16: dinv*(x@W1)
__device__ __align__(16) float  g_h  [(size_t)NNODES * C1];  // fp32 hidden
__device__ __align__(16) __half g_t2h[(size_t)NNODES * C2];  // fp16: dinv*(h@[Wmu|Wlv])
__device__ __align__(16) float  g_acc2[(size_t)NNODES * C2]; // fp32 aggregated sums

// ---------------- CSR build ----------------
__global__ void zero_cnt(int M) {
    int i = blockIdx.x * blockDim.x + threadIdx.x;
    if (i < M) g_cnt[i] = 0;
}
__global__ void count_deg(const int* __restrict__ ei, int E) {
    int e = blockIdx.x * blockDim.x + threadIdx.x;
    if (e < E) atomicAdd(&g_cnt[ei[(size_t)E + e]], 1);
}
__global__ void compute_dinv(int M) {
    int i = blockIdx.x * blockDim.x + threadIdx.x;
    if (i < M) g_dinv[i] = rsqrtf((float)(g_cnt[i] + 1));
}
__global__ __launch_bounds__(SCAN_B) void scan_local(int M) {
    __shared__ int sh[SCAN_B];
    int tid = threadIdx.x;
    int i = blockIdx.x * SCAN_B + tid;
    int v = (i < M) ? g_cnt[i] : 0;
    sh[tid] = v;
    __syncthreads();
#pragma unroll
    for (int off = 1; off < SCAN_B; off <<= 1) {
        int t = (tid >= off) ? sh[tid - off] : 0;
        __syncthreads();
        sh[tid] += t;
        __syncthreads();
    }
    if (i < M) g_rowptr[i] = sh[tid] - v;
    if (tid == SCAN_B - 1) g_bsum[blockIdx.x] = sh[tid];
}
__global__ void scan_bsums() {
    if (threadIdx.x == 0) {
        int acc = 0;
        for (int b = 0; b < NBLK; b++) { g_boff[b] = acc; acc += g_bsum[b]; }
    }
}
__global__ void scan_apply(int M) {
    int i = blockIdx.x * blockDim.x + threadIdx.x;
    if (i < M) {
        int r = g_rowptr[i] + g_boff[i / SCAN_B];
        g_rowptr[i] = r;
        g_cursor[i] = r;
    }
}
__global__ void fill_csr(const int* __restrict__ ei, int E) {
    int e = blockIdx.x * blockDim.x + threadIdx.x;
    if (e < E) {
        int s = ei[e];
        int d = ei[(size_t)E + e];
        int pos = atomicAdd(&g_cursor[d], 1);
        g_srclist[pos] = s;
    }
}

// ---------------- TF32 tensor-core GEMM, dinv-scaled fp16 epilogue ----------------
#define TBM 128
#define TBN 64
#define TBK 32
#define AS_STRIDE (TBK + 4)
#define BS_STRIDE (TBN + 8)

__device__ __forceinline__ float to_tf32(float v) {
    uint32_t u;
    asm("cvt.rna.tf32.f32 %0, %1;" : "=r"(u) : "f"(v));
    return __uint_as_float(u);
}

__global__ __launch_bounds__(256) void gemm_tf32_h(
    const float* __restrict__ A, int lda,
    const float* __restrict__ B, int ldb,
    __half* __restrict__ Ct, int ldc, int col_off,
    const float* __restrict__ dinv, int M, int K)
{
    __shared__ float As[TBM][AS_STRIDE];
    __shared__ float Bs[TBK][BS_STRIDE];

    const int tid = threadIdx.x;
    const int lane = tid & 31;
    const int warp = tid >> 5;
    const int wm = warp & 3;
    const int wn = warp >> 2;
    const int gid = lane >> 2;
    const int q = lane & 3;
    const int row0 = blockIdx.x * TBM;
    const int bcol0 = blockIdx.y * TBN;

    float c[2][4][4];
#pragma unroll
    for (int mt = 0; mt < 2; mt++)
#pragma unroll
        for (int nt = 0; nt < 4; nt++)
#pragma unroll
            for (int r = 0; r < 4; r++) c[mt][nt][r] = 0.f;

    for (int k0 = 0; k0 < K; k0 += TBK) {
#pragma unroll
        for (int i = 0; i < 4; i++) {
            int idx = tid + i * 256;
            int r = idx >> 3;
            int c4 = (idx & 7) << 2;
            int gr = row0 + r;
            float4 v = (gr < M) ? *(const float4*)(A + (size_t)gr * lda + k0 + c4)
                                : make_float4(0.f, 0.f, 0.f, 0.f);
            As[r][c4 + 0] = to_tf32(v.x);
            As[r][c4 + 1] = to_tf32(v.y);
            As[r][c4 + 2] = to_tf32(v.z);
            As[r][c4 + 3] = to_tf32(v.w);
        }
#pragma unroll
        for (int i = 0; i < 2; i++) {
            int idx = tid + i * 256;
            int r = idx >> 4;
            int c4 = (idx & 15) << 2;
            float4 v = *(const float4*)(B + (size_t)(k0 + r) * ldb + bcol0 + c4);
            Bs[r][c4 + 0] = to_tf32(v.x);
            Bs[r][c4 + 1] = to_tf32(v.y);
            Bs[r][c4 + 2] = to_tf32(v.z);
            Bs[r][c4 + 3] = to_tf32(v.w);
        }
        __syncthreads();

#pragma unroll
        for (int ks = 0; ks < TBK / 8; ks++) {
            int kb = ks * 8;
            uint32_t a[2][4], b[4][2];
#pragma unroll
            for (int mt = 0; mt < 2; mt++) {
                int r = wm * 32 + mt * 16;
                a[mt][0] = __float_as_uint(As[r + gid][kb + q]);
                a[mt][1] = __float_as_uint(As[r + gid + 8][kb + q]);
                a[mt][2] = __float_as_uint(As[r + gid][kb + q + 4]);
                a[mt][3] = __float_as_uint(As[r + gid + 8][kb + q + 4]);
            }
#pragma unroll
            for (int nt = 0; nt < 4; nt++) {
                int cc = wn * 32 + nt * 8 + gid;
                b[nt][0] = __float_as_uint(Bs[kb + q][cc]);
                b[nt][1] = __float_as_uint(Bs[kb + q + 4][cc]);
            }
#pragma unroll
            for (int mt = 0; mt < 2; mt++)
#pragma unroll
                for (int nt = 0; nt < 4; nt++)
                    asm volatile(
                        "mma.sync.aligned.m16n8k8.row.col.f32.tf32.tf32.f32 "
                        "{%0,%1,%2,%3}, {%4,%5,%6,%7}, {%8,%9}, {%0,%1,%2,%3};"
                        : "+f"(c[mt][nt][0]), "+f"(c[mt][nt][1]),
                          "+f"(c[mt][nt][2]), "+f"(c[mt][nt][3])
                        : "r"(a[mt][0]), "r"(a[mt][1]), "r"(a[mt][2]), "r"(a[mt][3]),
                          "r"(b[nt][0]), "r"(b[nt][1]));
        }
        __syncthreads();
    }

    // epilogue: scale by dinv[row], store half2
#pragma unroll
    for (int mt = 0; mt < 2; mt++) {
        int r0 = row0 + wm * 32 + mt * 16 + gid;
        int r1 = r0 + 8;
        float dv0 = (r0 < M) ? dinv[r0] : 0.f;
        float dv1 = (r1 < M) ? dinv[r1] : 0.f;
#pragma unroll
        for (int nt = 0; nt < 4; nt++) {
            int cc = col_off + bcol0 + wn * 32 + nt * 8 + 2 * q;
            if (r0 < M)
                *(__half2*)(Ct + (size_t)r0 * ldc + cc) =
                    __floats2half2_rn(c[mt][nt][0] * dv0, c[mt][nt][1] * dv0);
            if (r1 < M)
                *(__half2*)(Ct + (size_t)r1 * ldc + cc) =
                    __floats2half2_rn(c[mt][nt][2] * dv1, c[mt][nt][3] * dv1);
        }
    }
}

// ---- fp16 accumulate helpers (fp32 accumulation) ----
__device__ __forceinline__ void hacc8(float* a, uint4 u) {
    const __half2* hp = (const __half2*)&u;
#pragma unroll
    for (int i = 0; i < 4; i++) {
        float2 f = __half22float2(hp[i]);
        a[2 * i] += f.x;
        a[2 * i + 1] += f.y;
    }
}
__device__ __forceinline__ void hacc4(float* a, uint2 u) {
    const __half2* hp = (const __half2*)&u;
#pragma unroll
    for (int i = 0; i < 2; i++) {
        float2 f = __half22float2(hp[i]);
        a[2 * i] += f.x;
        a[2 * i + 1] += f.y;
    }
}

// ---------------- gather layer 1: h = relu(dinv*(self + sum t1h[src]) + b1) ----------------
// warp per dst node; lane covers channels [lane*8, lane*8+8)
__global__ __launch_bounds__(256) void gather1(const float* __restrict__ b1, int M)
{
    int w = (blockIdx.x * blockDim.x + threadIdx.x) >> 5;
    if (w >= M) return;
    int lane = threadIdx.x & 31;
    int base = g_rowptr[w];
    int deg = g_cnt[w];

    float a[8];
    {
        uint4 u = ((const uint4*)(g_t1h + (size_t)w * C1))[lane];
#pragma unroll
        for (int i = 0; i < 8; i++) a[i] = 0.f;
        hacc8(a, u);
    }

    for (int j = 0; j < deg; j += 32) {
        int nrem = min(32, deg - j);
        int idx = (j + lane < deg) ? g_srclist[base + j + lane] : 0;
        int k = 0;
        for (; k + 3 < nrem; k += 4) {
            int s0 = __shfl_sync(0xffffffff, idx, k);
            int s1 = __shfl_sync(0xffffffff, idx, k + 1);
            int s2 = __shfl_sync(0xffffffff, idx, k + 2);
            int s3 = __shfl_sync(0xffffffff, idx, k + 3);
            uint4 u0 = ((const uint4*)(g_t1h + (size_t)s0 * C1))[lane];
            uint4 u1 = ((const uint4*)(g_t1h + (size_t)s1 * C1))[lane];
            uint4 u2 = ((const uint4*)(g_t1h + (size_t)s2 * C1))[lane];
            uint4 u3 = ((const uint4*)(g_t1h + (size_t)s3 * C1))[lane];
            hacc8(a, u0); hacc8(a, u1); hacc8(a, u2); hacc8(a, u3);
        }
        for (; k < nrem; k++) {
            int s0 = __shfl_sync(0xffffffff, idx, k);
            hacc8(a, ((const uint4*)(g_t1h + (size_t)s0 * C1))[lane]);
        }
    }

    float dv = g_dinv[w];
    float4 bb0 = ((const float4*)b1)[lane * 2];
    float4 bb1 = ((const float4*)b1)[lane * 2 + 1];
    float4 o0, o1;
    o0.x = fmaxf(fmaf(dv, a[0], bb0.x), 0.f);
    o0.y = fmaxf(fmaf(dv, a[1], bb0.y), 0.f);
    o0.z = fmaxf(fmaf(dv, a[2], bb0.z), 0.f);
    o0.w = fmaxf(fmaf(dv, a[3], bb0.w), 0.f);
    o1.x = fmaxf(fmaf(dv, a[4], bb1.x), 0.f);
    o1.y = fmaxf(fmaf(dv, a[5], bb1.y), 0.f);
    o1.z = fmaxf(fmaf(dv, a[6], bb1.z), 0.f);
    o1.w = fmaxf(fmaf(dv, a[7], bb1.w), 0.f);
    float4* hp = (float4*)(g_h + (size_t)w * C1 + lane * 8);
    hp[0] = o0;
    hp[1] = o1;
}

// ---------------- gather layer 2: acc2 = self + sum t2h[src]  (fp32 out) ----------------
// warp per dst node; lane covers channels [lane*4, lane*4+4)
__global__ __launch_bounds__(256) void gather2(int M)
{
    int w = (blockIdx.x * blockDim.x + threadIdx.x) >> 5;
    if (w >= M) return;
    int lane = threadIdx.x & 31;
    int base = g_rowptr[w];
    int deg = g_cnt[w];

    float a[4] = {0.f, 0.f, 0.f, 0.f};
    hacc4(a, ((const uint2*)(g_t2h + (size_t)w * C2))[lane]);

    for (int j = 0; j < deg; j += 32) {
        int nrem = min(32, deg - j);
        int idx = (j + lane < deg) ? g_srclist[base + j + lane] : 0;
        int k = 0;
        for (; k + 3 < nrem; k += 4) {
            int s0 = __shfl_sync(0xffffffff, idx, k);
            int s1 = __shfl_sync(0xffffffff, idx, k + 1);
            int s2 = __shfl_sync(0xffffffff, idx, k + 2);
            int s3 = __shfl_sync(0xffffffff, idx, k + 3);
            uint2 u0 = ((const uint2*)(g_t2h + (size_t)s0 * C2))[lane];
            uint2 u1 = ((const uint2*)(g_t2h + (size_t)s1 * C2))[lane];
            uint2 u2 = ((const uint2*)(g_t2h + (size_t)s2 * C2))[lane];
            uint2 u3 = ((const uint2*)(g_t2h + (size_t)s3 * C2))[lane];
            hacc4(a, u0); hacc4(a, u1); hacc4(a, u2); hacc4(a, u3);
        }
        for (; k < nrem; k++) {
            int s0 = __shfl_sync(0xffffffff, idx, k);
            hacc4(a, ((const uint2*)(g_t2h + (size_t)s0 * C2))[lane]);
        }
    }
    *(float4*)(g_acc2 + (size_t)w * C2 + lane * 4) = make_float4(a[0], a[1], a[2], a[3]);
}

// ---------------- head: mu/lv finalize + reparameterize + classifier ----------------
__global__ __launch_bounds__(256) void head_kernel(
    const float* __restrict__ b_mu, const float* __restrict__ b_lv,
    const float* __restrict__ W_c, const float* __restrict__ b_c,
    const float* __restrict__ eps,
    float* __restrict__ out, int M)
{
    __shared__ float Wc[64 * 64];
    __shared__ float zs[4][64];
    int tid = threadIdx.x;
    for (int i = tid; i < 64 * 64; i += 256) Wc[i] = W_c[i];

    int c = tid & 63;
    int sub = tid >> 6;
    int n = blockIdx.x * 4 + sub;
    size_t MO = (size_t)M * 64;

    if (n < M) {
        float dv = g_dinv[n];
        float mu = fmaf(dv, g_acc2[(size_t)n * C2 + c], b_mu[c]);
        float lv = fmaf(dv, g_acc2[(size_t)n * C2 + 64 + c], b_lv[c]);
        float z = fmaf(eps[(size_t)n * 64 + c], __expf(0.5f * lv), mu);
        out[MO + (size_t)n * 64 + c] = mu;
        out[2 * MO + (size_t)n * 64 + c] = lv;
        zs[sub][c] = z;
    }
    __syncthreads();
    if (n < M) {
        float s = b_c[c];
#pragma unroll
        for (int k = 0; k < 64; k++) s = fmaf(zs[sub][k], Wc[k * 64 + c], s);
        out[(size_t)n * 64 + c] = s;
    }
}

extern "C" void kernel_launch(void* const* d_in, const int* in_sizes, int n_in,
                              void* d_out, int out_size) {
    const float* x    = (const float*)d_in[0];
    const int*   ei   = (const int*)d_in[1];
    const float* W1   = (const float*)d_in[2];
    const float* b1   = (const float*)d_in[3];
    const float* W_mu = (const float*)d_in[4];
    const float* b_mu = (const float*)d_in[5];
    const float* W_lv = (const float*)d_in[6];
    const float* b_lv = (const float*)d_in[7];
    const float* W_c  = (const float*)d_in[8];
    const float* b_c  = (const float*)d_in[9];
    const float* eps  = (const float*)d_in[10];
    float* out = (float*)d_out;

    const int M = in_sizes[0] / 512;   // 100000
    const int E = in_sizes[1] / 2;     // 3200000

    float *dinv, *h;
    __half *t1h, *t2h;
    cudaGetSymbolAddress((void**)&dinv, g_dinv);
    cudaGetSymbolAddress((void**)&t1h,  g_t1h);
    cudaGetSymbolAddress((void**)&h,    g_h);
    cudaGetSymbolAddress((void**)&t2h,  g_t2h);

    // ---- CSR build + dinv ----
    zero_cnt<<<(M + 255) / 256, 256>>>(M);
    count_deg<<<(E + 511) / 512, 512>>>(ei, E);
    compute_dinv<<<(M + 255) / 256, 256>>>(M);
    scan_local<<<NBLK, SCAN_B>>>(M);
    scan_bsums<<<1, 32>>>();
    scan_apply<<<(M + 255) / 256, 256>>>(M);
    fill_csr<<<(E + 511) / 512, 512>>>(ei, E);

    // ---- layer 1 ----
    {
        dim3 grid((M + TBM - 1) / TBM, C1 / TBN);
        gemm_tf32_h<<<grid, 256>>>(x, 512, W1, C1, t1h, C1, 0, dinv, M, 512);
    }
    gather1<<<(M * 32 + 255) / 256, 256>>>(b1, M);

    // ---- layer 2 (fused mu|logvar) ----
    {
        dim3 grid((M + TBM - 1) / TBM, 1);
        gemm_tf32_h<<<grid, 256>>>(h, C1, W_mu, 64, t2h, C2, 0,  dinv, M, C1);
        gemm_tf32_h<<<grid, 256>>>(h, C1, W_lv, 64, t2h, C2, 64, dinv, M, C1);
    }
    gather2<<<(M * 32 + 255) / 256, 256>>>(M);

    // ---- head ----
    head_kernel<<<(M + 3) / 4, 256>>>(b_mu, b_lv, W_c, b_c, eps, out, M);
}

// round 6
// speedup vs baseline: 5.3525x; 1.0141x over previous
#include <cuda_runtime.h>
#include <cuda_fp16.h>
#include <cstddef>
#include <cstdint>

#define NNODES 100000
#define NEDGES 3200000
#define C1 256
#define C2 128
#define SCAN_B 1024
#define NBLK ((NNODES + SCAN_B - 1) / SCAN_B)   // 98

// ---- scratch (static device globals) ----
__device__ int g_cnt   [NNODES];
__device__ int g_rowptr[NNODES];
__device__ int g_cursor[NNODES];
__device__ int g_bsum  [NBLK];
__device__ int g_boff  [NBLK];
__device__ int g_srclist[NEDGES];
__device__ __align__(16) float  g_dinv[NNODES];
__device__ __align__(16) __half g_t1h[(size_t)NNODES * C1];
__device__ __align__(16) float  g_h  [(size_t)NNODES * C1];
__device__ __align__(16) __half g_t2h[(size_t)NNODES * C2];
__device__ __align__(16) float  g_acc2[(size_t)NNODES * C2];

// ---------------- CSR build ----------------
__global__ void zero_cnt(int M) {
    int i = blockIdx.x * blockDim.x + threadIdx.x;
    if (i < M) g_cnt[i] = 0;
}
__global__ void count_deg(const int* __restrict__ ei, int E) {
    int e = blockIdx.x * blockDim.x + threadIdx.x;
    if (e < E) atomicAdd(&g_cnt[ei[(size_t)E + e]], 1);
}
__global__ __launch_bounds__(SCAN_B) void scan_local(int M) {
    __shared__ int sh[SCAN_B];
    int tid = threadIdx.x;
    int i = blockIdx.x * SCAN_B + tid;
    int v = (i < M) ? g_cnt[i] : 0;
    if (i < M) g_dinv[i] = rsqrtf((float)(v + 1));   // fused dinv
    sh[tid] = v;
    __syncthreads();
#pragma unroll
    for (int off = 1; off < SCAN_B; off <<= 1) {
        int t = (tid >= off) ? sh[tid - off] : 0;
        __syncthreads();
        sh[tid] += t;
        __syncthreads();
    }
    if (i < M) g_rowptr[i] = sh[tid] - v;
    if (tid == SCAN_B - 1) g_bsum[blockIdx.x] = sh[tid];
}
__global__ void scan_bsums() {
    if (threadIdx.x == 0) {
        int acc = 0;
        for (int b = 0; b < NBLK; b++) { g_boff[b] = acc; acc += g_bsum[b]; }
    }
}
__global__ void scan_apply(int M) {
    int i = blockIdx.x * blockDim.x + threadIdx.x;
    if (i < M) {
        int r = g_rowptr[i] + g_boff[i / SCAN_B];
        g_rowptr[i] = r;
        g_cursor[i] = r;
    }
}
__global__ void fill_csr(const int* __restrict__ ei, int E) {
    int e = blockIdx.x * blockDim.x + threadIdx.x;
    if (e < E) {
        int s = ei[e];
        int d = ei[(size_t)E + e];
        int pos = atomicAdd(&g_cursor[d], 1);
        g_srclist[pos] = s;
    }
}

// ---------------- fp16 tensor-core GEMM (m16n8k16), fp32 acc, dinv-scaled fp16 out ----------------
// BM=128 BN=64 BK=32, 256 threads, double-buffered smem + register prefetch.
// B select: blockIdx.y < nby1 -> B1 col-tile blockIdx.y; else B2 col-tile (blockIdx.y - nby1).
#define TBM 128
#define TBN 64
#define TBK 32
#define AST 40   // half stride (80B = 20 banks) -> conflict-free frags
#define BST 40

__global__ __launch_bounds__(256) void gemm_h16(
    const float* __restrict__ A, int lda,
    const float* __restrict__ B1, const float* __restrict__ B2,
    int ldb, int nby1,
    __half* __restrict__ Ct, int ldc,
    const float* __restrict__ dinv, int M, int K)
{
    __shared__ __half As[2][TBM][AST];
    __shared__ __half BsT[2][TBN][BST];   // transposed: [n][k]

    const int tid = threadIdx.x;
    const int lane = tid & 31;
    const int warp = tid >> 5;
    const int wm = warp & 3;
    const int wn = warp >> 2;
    const int gid = lane >> 2;
    const int q = lane & 3;
    const int row0 = blockIdx.x * TBM;

    const float* B = (blockIdx.y < nby1) ? B1 : B2;
    const int bcol0 = (blockIdx.y < nby1) ? blockIdx.y * TBN
                                          : (blockIdx.y - nby1) * TBN;
    const int ocol0 = blockIdx.y * TBN;

    float c[2][4][4];
#pragma unroll
    for (int mt = 0; mt < 2; mt++)
#pragma unroll
        for (int nt = 0; nt < 4; nt++)
#pragma unroll
            for (int r = 0; r < 4; r++) c[mt][nt][r] = 0.f;

    const int nk = K / TBK;
    float4 Av[4], Bv[2];

    // ---- gmem load of tile t into regs ----
    auto load_tile = [&](int t) {
        int k0 = t * TBK;
#pragma unroll
        for (int i = 0; i < 4; i++) {
            int idx = tid + i * 256;
            int r = idx >> 3;
            int c4 = (idx & 7) << 2;
            int gr = row0 + r;
            Av[i] = (gr < M) ? *(const float4*)(A + (size_t)gr * lda + k0 + c4)
                             : make_float4(0.f, 0.f, 0.f, 0.f);
        }
#pragma unroll
        for (int i = 0; i < 2; i++) {
            int idx = tid + i * 256;
            int r = idx >> 4;
            int c4 = (idx & 15) << 2;
            Bv[i] = *(const float4*)(B + (size_t)(k0 + r) * ldb + bcol0 + c4);
        }
    };
    // ---- store regs into smem buffer ----
    auto store_tile = [&](int buf) {
#pragma unroll
        for (int i = 0; i < 4; i++) {
            int idx = tid + i * 256;
            int r = idx >> 3;
            int c4 = (idx & 7) << 2;
            __half2* p = (__half2*)&As[buf][r][c4];
            p[0] = __floats2half2_rn(Av[i].x, Av[i].y);
            p[1] = __floats2half2_rn(Av[i].z, Av[i].w);
        }
#pragma unroll
        for (int i = 0; i < 2; i++) {
            int idx = tid + i * 256;
            int r = idx >> 4;
            int c4 = (idx & 15) << 2;
            BsT[buf][c4 + 0][r] = __float2half_rn(Bv[i].x);
            BsT[buf][c4 + 1][r] = __float2half_rn(Bv[i].y);
            BsT[buf][c4 + 2][r] = __float2half_rn(Bv[i].z);
            BsT[buf][c4 + 3][r] = __float2half_rn(Bv[i].w);
        }
    };

    load_tile(0);
    store_tile(0);
    __syncthreads();

    for (int t = 0; t < nk; t++) {
        int buf = t & 1;
        if (t + 1 < nk) load_tile(t + 1);

#pragma unroll
        for (int ks = 0; ks < TBK / 16; ks++) {
            int kb = ks * 16;
            uint32_t a[2][4], b[4][2];
#pragma unroll
            for (int mt = 0; mt < 2; mt++) {
                int r = wm * 32 + mt * 16 + gid;
                a[mt][0] = *(const uint32_t*)&As[buf][r][kb + 2 * q];
                a[mt][1] = *(const uint32_t*)&As[buf][r + 8][kb + 2 * q];
                a[mt][2] = *(const uint32_t*)&As[buf][r][kb + 2 * q + 8];
                a[mt][3] = *(const uint32_t*)&As[buf][r + 8][kb + 2 * q + 8];
            }
#pragma unroll
            for (int nt = 0; nt < 4; nt++) {
                int cc = wn * 32 + nt * 8 + gid;
                b[nt][0] = *(const uint32_t*)&BsT[buf][cc][kb + 2 * q];
                b[nt][1] = *(const uint32_t*)&BsT[buf][cc][kb + 2 * q + 8];
            }
#pragma unroll
            for (int mt = 0; mt < 2; mt++)
#pragma unroll
                for (int nt = 0; nt < 4; nt++)
                    asm volatile(
                        "mma.sync.aligned.m16n8k16.row.col.f32.f16.f16.f32 "
                        "{%0,%1,%2,%3}, {%4,%5,%6,%7}, {%8,%9}, {%0,%1,%2,%3};"
                        : "+f"(c[mt][nt][0]), "+f"(c[mt][nt][1]),
                          "+f"(c[mt][nt][2]), "+f"(c[mt][nt][3])
                        : "r"(a[mt][0]), "r"(a[mt][1]), "r"(a[mt][2]), "r"(a[mt][3]),
                          "r"(b[nt][0]), "r"(b[nt][1]));
        }

        if (t + 1 < nk) {
            store_tile(buf ^ 1);
            __syncthreads();
        }
    }

    // epilogue: scale by dinv[row], store half2
#pragma unroll
    for (int mt = 0; mt < 2; mt++) {
        int r0 = row0 + wm * 32 + mt * 16 + gid;
        int r1 = r0 + 8;
        float dv0 = (r0 < M) ? dinv[r0] : 0.f;
        float dv1 = (r1 < M) ? dinv[r1] : 0.f;
#pragma unroll
        for (int nt = 0; nt < 4; nt++) {
            int cc = ocol0 + wn * 32 + nt * 8 + 2 * q;
            if (r0 < M)
                *(__half2*)(Ct + (size_t)r0 * ldc + cc) =
                    __floats2half2_rn(c[mt][nt][0] * dv0, c[mt][nt][1] * dv0);
            if (r1 < M)
                *(__half2*)(Ct + (size_t)r1 * ldc + cc) =
                    __floats2half2_rn(c[mt][nt][2] * dv1, c[mt][nt][3] * dv1);
        }
    }
}

// ---- fp16 accumulate helpers ----
__device__ __forceinline__ void hacc8(float* a, uint4 u) {
    const __half2* hp = (const __half2*)&u;
#pragma unroll
    for (int i = 0; i < 4; i++) {
        float2 f = __half22float2(hp[i]);
        a[2 * i] += f.x;
        a[2 * i + 1] += f.y;
    }
}
__device__ __forceinline__ void hacc4(float* a, uint2 u) {
    const __half2* hp = (const __half2*)&u;
#pragma unroll
    for (int i = 0; i < 2; i++) {
        float2 f = __half22float2(hp[i]);
        a[2 * i] += f.x;
        a[2 * i + 1] += f.y;
    }
}

// ---------------- gather layer 1 ----------------
__global__ __launch_bounds__(256) void gather1(const float* __restrict__ b1, int M)
{
    int w = (blockIdx.x * blockDim.x + threadIdx.x) >> 5;
    if (w >= M) return;
    int lane = threadIdx.x & 31;
    int base = g_rowptr[w];
    int deg = g_cnt[w];

    float a[8];
    {
        uint4 u = ((const uint4*)(g_t1h + (size_t)w * C1))[lane];
#pragma unroll
        for (int i = 0; i < 8; i++) a[i] = 0.f;
        hacc8(a, u);
    }

    for (int j = 0; j < deg; j += 32) {
        int nrem = min(32, deg - j);
        int idx = (j + lane < deg) ? g_srclist[base + j + lane] : 0;
        int k = 0;
        for (; k + 3 < nrem; k += 4) {
            int s0 = __shfl_sync(0xffffffff, idx, k);
            int s1 = __shfl_sync(0xffffffff, idx, k + 1);
            int s2 = __shfl_sync(0xffffffff, idx, k + 2);
            int s3 = __shfl_sync(0xffffffff, idx, k + 3);
            uint4 u0 = ((const uint4*)(g_t1h + (size_t)s0 * C1))[lane];
            uint4 u1 = ((const uint4*)(g_t1h + (size_t)s1 * C1))[lane];
            uint4 u2 = ((const uint4*)(g_t1h + (size_t)s2 * C1))[lane];
            uint4 u3 = ((const uint4*)(g_t1h + (size_t)s3 * C1))[lane];
            hacc8(a, u0); hacc8(a, u1); hacc8(a, u2); hacc8(a, u3);
        }
        for (; k < nrem; k++) {
            int s0 = __shfl_sync(0xffffffff, idx, k);
            hacc8(a, ((const uint4*)(g_t1h + (size_t)s0 * C1))[lane]);
        }
    }

    float dv = g_dinv[w];
    float4 bb0 = ((const float4*)b1)[lane * 2];
    float4 bb1 = ((const float4*)b1)[lane * 2 + 1];
    float4 o0, o1;
    o0.x = fmaxf(fmaf(dv, a[0], bb0.x), 0.f);
    o0.y = fmaxf(fmaf(dv, a[1], bb0.y), 0.f);
    o0.z = fmaxf(fmaf(dv, a[2], bb0.z), 0.f);
    o0.w = fmaxf(fmaf(dv, a[3], bb0.w), 0.f);
    o1.x = fmaxf(fmaf(dv, a[4], bb1.x), 0.f);
    o1.y = fmaxf(fmaf(dv, a[5], bb1.y), 0.f);
    o1.z = fmaxf(fmaf(dv, a[6], bb1.z), 0.f);
    o1.w = fmaxf(fmaf(dv, a[7], bb1.w), 0.f);
    float4* hp = (float4*)(g_h + (size_t)w * C1 + lane * 8);
    hp[0] = o0;
    hp[1] = o1;
}

// ---------------- gather layer 2 ----------------
__global__ __launch_bounds__(256) void gather2(int M)
{
    int w = (blockIdx.x * blockDim.x + threadIdx.x) >> 5;
    if (w >= M) return;
    int lane = threadIdx.x & 31;
    int base = g_rowptr[w];
    int deg = g_cnt[w];

    float a[4] = {0.f, 0.f, 0.f, 0.f};
    hacc4(a, ((const uint2*)(g_t2h + (size_t)w * C2))[lane]);

    for (int j = 0; j < deg; j += 32) {
        int nrem = min(32, deg - j);
        int idx = (j + lane < deg) ? g_srclist[base + j + lane] : 0;
        int k = 0;
        for (; k + 3 < nrem; k += 4) {
            int s0 = __shfl_sync(0xffffffff, idx, k);
            int s1 = __shfl_sync(0xffffffff, idx, k + 1);
            int s2 = __shfl_sync(0xffffffff, idx, k + 2);
            int s3 = __shfl_sync(0xffffffff, idx, k + 3);
            uint2 u0 = ((const uint2*)(g_t2h + (size_t)s0 * C2))[lane];
            uint2 u1 = ((const uint2*)(g_t2h + (size_t)s1 * C2))[lane];
            uint2 u2 = ((const uint2*)(g_t2h + (size_t)s2 * C2))[lane];
            uint2 u3 = ((const uint2*)(g_t2h + (size_t)s3 * C2))[lane];
            hacc4(a, u0); hacc4(a, u1); hacc4(a, u2); hacc4(a, u3);
        }
        for (; k < nrem; k++) {
            int s0 = __shfl_sync(0xffffffff, idx, k);
            hacc4(a, ((const uint2*)(g_t2h + (size_t)s0 * C2))[lane]);
        }
    }
    *(float4*)(g_acc2 + (size_t)w * C2 + lane * 4) = make_float4(a[0], a[1], a[2], a[3]);
}

// ---------------- head ----------------
__global__ __launch_bounds__(256) void head_kernel(
    const float* __restrict__ b_mu, const float* __restrict__ b_lv,
    const float* __restrict__ W_c, const float* __restrict__ b_c,
    const float* __restrict__ eps,
    float* __restrict__ out, int M)
{
    __shared__ float Wc[64 * 64];
    __shared__ float zs[4][64];
    int tid = threadIdx.x;
    for (int i = tid; i < 64 * 64; i += 256) Wc[i] = W_c[i];

    int c = tid & 63;
    int sub = tid >> 6;
    int n = blockIdx.x * 4 + sub;
    size_t MO = (size_t)M * 64;

    if (n < M) {
        float dv = g_dinv[n];
        float mu = fmaf(dv, g_acc2[(size_t)n * C2 + c], b_mu[c]);
        float lv = fmaf(dv, g_acc2[(size_t)n * C2 + 64 + c], b_lv[c]);
        float z = fmaf(eps[(size_t)n * 64 + c], __expf(0.5f * lv), mu);
        out[MO + (size_t)n * 64 + c] = mu;
        out[2 * MO + (size_t)n * 64 + c] = lv;
        zs[sub][c] = z;
    }
    __syncthreads();
    if (n < M) {
        float s = b_c[c];
#pragma unroll
        for (int k = 0; k < 64; k++) s = fmaf(zs[sub][k], Wc[k * 64 + c], s);
        out[(size_t)n * 64 + c] = s;
    }
}

extern "C" void kernel_launch(void* const* d_in, const int* in_sizes, int n_in,
                              void* d_out, int out_size) {
    const float* x    = (const float*)d_in[0];
    const int*   ei   = (const int*)d_in[1];
    const float* W1   = (const float*)d_in[2];
    const float* b1   = (const float*)d_in[3];
    const float* W_mu = (const float*)d_in[4];
    const float* b_mu = (const float*)d_in[5];
    const float* W_lv = (const float*)d_in[6];
    const float* b_lv = (const float*)d_in[7];
    const float* W_c  = (const float*)d_in[8];
    const float* b_c  = (const float*)d_in[9];
    const float* eps  = (const float*)d_in[10];
    float* out = (float*)d_out;

    const int M = in_sizes[0] / 512;   // 100000
    const int E = in_sizes[1] / 2;     // 3200000

    float *dinv, *h;
    __half *t1h, *t2h;
    cudaGetSymbolAddress((void**)&dinv, g_dinv);
    cudaGetSymbolAddress((void**)&t1h,  g_t1h);
    cudaGetSymbolAddress((void**)&h,    g_h);
    cudaGetSymbolAddress((void**)&t2h,  g_t2h);

    // ---- CSR build + dinv ----
    zero_cnt<<<(M + 255) / 256, 256>>>(M);
    count_deg<<<(E + 511) / 512, 512>>>(ei, E);
    scan_local<<<NBLK, SCAN_B>>>(M);
    scan_bsums<<<1, 32>>>();
    scan_apply<<<(M + 255) / 256, 256>>>(M);
    fill_csr<<<(E + 511) / 512, 512>>>(ei, E);

    // ---- layer 1: t1h = dinv * (x @ W1)  [M x 256] ----
    {
        dim3 grid((M + TBM - 1) / TBM, C1 / TBN);
        gemm_h16<<<grid, 256>>>(x, 512, W1, W1, C1, C1 / TBN, t1h, C1, dinv, M, 512);
    }
    gather1<<<(M * 32 + 255) / 256, 256>>>(b1, M);

    // ---- layer 2 (one launch, grid.y picks W_mu / W_lv) ----
    {
        dim3 grid((M + TBM - 1) / TBM, 2);
        gemm_h16<<<grid, 256>>>(h, C1, W_mu, W_lv, 64, 1, t2h, C2, dinv, M, C1);
    }
    gather2<<<(M * 32 + 255) / 256, 256>>>(M);

    // ---- head ----
    head_kernel<<<(M + 3) / 4, 256>>>(b_mu, b_lv, W_c, b_c, eps, out, M);
}

// round 7
// speedup vs baseline: 6.4140x; 1.1983x over previous
#include <cuda_runtime.h>
#include <cuda_fp16.h>
#include <cstddef>
#include <cstdint>

#define NNODES 100000
#define NEDGES 3200000
#define C1 256
#define C2 128
#define SCAN_B 1024
#define NBLK ((NNODES + SCAN_B - 1) / SCAN_B)   // 98

// ---- scratch (static device globals) ----
__device__ int g_cnt   [NNODES];
__device__ int g_rowptr[NNODES];
__device__ int g_cursor[NNODES];
__device__ int g_bsum  [NBLK];
__device__ int g_srclist[NEDGES];
__device__ __align__(16) float  g_dinv[NNODES];
__device__ __align__(16) __half g_t1h[(size_t)NNODES * C1];
__device__ __align__(16) float  g_h  [(size_t)NNODES * C1];
__device__ __align__(16) __half g_t2h[(size_t)NNODES * C2];
__device__ __align__(16) float  g_acc2[(size_t)NNODES * C2];

// ---------------- CSR build ----------------
__global__ void zero_cnt(int M) {
    int i = blockIdx.x * blockDim.x + threadIdx.x;
    if (i < M) g_cnt[i] = 0;
}
__global__ void count_deg(const int* __restrict__ ei, int E) {
    int e = blockIdx.x * blockDim.x + threadIdx.x;
    if (e < E) atomicAdd(&g_cnt[ei[(size_t)E + e]], 1);
}
__global__ __launch_bounds__(SCAN_B) void scan_local(int M) {
    __shared__ int sh[SCAN_B];
    int tid = threadIdx.x;
    int i = blockIdx.x * SCAN_B + tid;
    int v = (i < M) ? g_cnt[i] : 0;
    if (i < M) g_dinv[i] = rsqrtf((float)(v + 1));
    sh[tid] = v;
    __syncthreads();
#pragma unroll
    for (int off = 1; off < SCAN_B; off <<= 1) {
        int t = (tid >= off) ? sh[tid - off] : 0;
        __syncthreads();
        sh[tid] += t;
        __syncthreads();
    }
    if (i < M) g_rowptr[i] = sh[tid] - v;
    if (tid == SCAN_B - 1) g_bsum[blockIdx.x] = sh[tid];
}
// scan_apply with per-block computation of the block-sum prefix (no scan_bsums kernel)
__global__ void scan_apply(int M) {
    __shared__ int s_off;
    int seg = (blockIdx.x * 256) / SCAN_B;
    if (threadIdx.x < 32) {
        int acc = 0;
        for (int j = threadIdx.x; j < seg; j += 32) acc += g_bsum[j];
#pragma unroll
        for (int o = 16; o; o >>= 1) acc += __shfl_down_sync(0xffffffff, acc, o);
        if (threadIdx.x == 0) s_off = acc;
    }
    __syncthreads();
    int i = blockIdx.x * 256 + threadIdx.x;
    if (i < M) {
        int r = g_rowptr[i] + s_off;
        g_rowptr[i] = r;
        g_cursor[i] = r;
    }
}
__global__ void fill_csr(const int* __restrict__ ei, int E) {
    int e = blockIdx.x * blockDim.x + threadIdx.x;
    if (e < E) {
        int s = ei[e];
        int d = ei[(size_t)E + e];
        int pos = atomicAdd(&g_cursor[d], 1);
        g_srclist[pos] = s;
    }
}

// ---------------- fp16 MMA GEMM with ldmatrix fragments ----------------
// BM=128 BN=64 BK=32, 256 threads, double-buffered smem, dinv-scaled fp16 out.
#define TBM 128
#define TBN 64
#define TBK 32
#define AST 40   // half stride: 80B rows -> ldmatrix conflict-free
#define BST 72   // half stride: 144B rows -> ldmatrix conflict-free

__device__ __forceinline__ void ldsm_x4(uint32_t& r0, uint32_t& r1, uint32_t& r2, uint32_t& r3,
                                        const void* p) {
    uint32_t addr = (uint32_t)__cvta_generic_to_shared(p);
    asm volatile("ldmatrix.sync.aligned.m8n8.x4.shared.b16 {%0,%1,%2,%3}, [%4];"
                 : "=r"(r0), "=r"(r1), "=r"(r2), "=r"(r3) : "r"(addr));
}
__device__ __forceinline__ void ldsm_x2t(uint32_t& r0, uint32_t& r1, const void* p) {
    uint32_t addr = (uint32_t)__cvta_generic_to_shared(p);
    asm volatile("ldmatrix.sync.aligned.m8n8.x2.trans.shared.b16 {%0,%1}, [%2];"
                 : "=r"(r0), "=r"(r1) : "r"(addr));
}

__global__ __launch_bounds__(256) void gemm_h16(
    const float* __restrict__ A, int lda,
    const float* __restrict__ B1, const float* __restrict__ B2,
    int ldb, int nby1,
    __half* __restrict__ Ct, int ldc,
    const float* __restrict__ dinv, int M, int K)
{
    __shared__ __align__(16) __half As[2][TBM][AST];
    __shared__ __align__(16) __half Bs[2][TBK][BST];   // [k][n]

    const int tid = threadIdx.x;
    const int lane = tid & 31;
    const int warp = tid >> 5;
    const int wm = warp & 3;
    const int wn = warp >> 2;
    const int gid = lane >> 2;
    const int q = lane & 3;
    const int row0 = blockIdx.x * TBM;

    const float* B = (blockIdx.y < nby1) ? B1 : B2;
    const int bcol0 = (blockIdx.y < nby1) ? blockIdx.y * TBN
                                          : (blockIdx.y - nby1) * TBN;
    const int ocol0 = blockIdx.y * TBN;

    float c[2][4][4];
#pragma unroll
    for (int mt = 0; mt < 2; mt++)
#pragma unroll
        for (int nt = 0; nt < 4; nt++)
#pragma unroll
            for (int r = 0; r < 4; r++) c[mt][nt][r] = 0.f;

    const int nk = K / TBK;
    float4 Av[4], Bv[2];

    auto load_tile = [&](int t) {
        int k0 = t * TBK;
#pragma unroll
        for (int i = 0; i < 4; i++) {
            int idx = tid + i * 256;
            int r = idx >> 3;
            int c4 = (idx & 7) << 2;
            int gr = row0 + r;
            Av[i] = (gr < M) ? *(const float4*)(A + (size_t)gr * lda + k0 + c4)
                             : make_float4(0.f, 0.f, 0.f, 0.f);
        }
#pragma unroll
        for (int i = 0; i < 2; i++) {
            int idx = tid + i * 256;
            int r = idx >> 4;
            int c4 = (idx & 15) << 2;
            Bv[i] = *(const float4*)(B + (size_t)(k0 + r) * ldb + bcol0 + c4);
        }
    };
    auto store_tile = [&](int buf) {
#pragma unroll
        for (int i = 0; i < 4; i++) {
            int idx = tid + i * 256;
            int r = idx >> 3;
            int c4 = (idx & 7) << 2;
            __half2 h01 = __floats2half2_rn(Av[i].x, Av[i].y);
            __half2 h23 = __floats2half2_rn(Av[i].z, Av[i].w);
            uint2 u = make_uint2(*(uint32_t*)&h01, *(uint32_t*)&h23);
            *(uint2*)&As[buf][r][c4] = u;
        }
#pragma unroll
        for (int i = 0; i < 2; i++) {
            int idx = tid + i * 256;
            int r = idx >> 4;
            int c4 = (idx & 15) << 2;
            __half2 h01 = __floats2half2_rn(Bv[i].x, Bv[i].y);
            __half2 h23 = __floats2half2_rn(Bv[i].z, Bv[i].w);
            uint2 u = make_uint2(*(uint32_t*)&h01, *(uint32_t*)&h23);
            *(uint2*)&Bs[buf][r][c4] = u;
        }
    };

    load_tile(0);
    store_tile(0);
    __syncthreads();

    // ldmatrix lane addressing
    const int a_row = (lane & 15);          // m offset within 16
    const int a_koff = (lane >> 4) << 3;    // 0 or 8
    const int b_krow = (lane & 15);         // k row (lanes 0-15 meaningful)

    for (int t = 0; t < nk; t++) {
        int buf = t & 1;
        if (t + 1 < nk) load_tile(t + 1);

#pragma unroll
        for (int ks = 0; ks < TBK / 16; ks++) {
            int kb = ks * 16;
            uint32_t a[2][4], b[4][2];
#pragma unroll
            for (int mt = 0; mt < 2; mt++) {
                const __half* p = &As[buf][wm * 32 + mt * 16 + a_row][kb + a_koff];
                ldsm_x4(a[mt][0], a[mt][1], a[mt][2], a[mt][3], p);
            }
#pragma unroll
            for (int nt = 0; nt < 4; nt++) {
                const __half* p = &Bs[buf][kb + b_krow][wn * 32 + nt * 8];
                ldsm_x2t(b[nt][0], b[nt][1], p);
            }
#pragma unroll
            for (int mt = 0; mt < 2; mt++)
#pragma unroll
                for (int nt = 0; nt < 4; nt++)
                    asm volatile(
                        "mma.sync.aligned.m16n8k16.row.col.f32.f16.f16.f32 "
                        "{%0,%1,%2,%3}, {%4,%5,%6,%7}, {%8,%9}, {%0,%1,%2,%3};"
                        : "+f"(c[mt][nt][0]), "+f"(c[mt][nt][1]),
                          "+f"(c[mt][nt][2]), "+f"(c[mt][nt][3])
                        : "r"(a[mt][0]), "r"(a[mt][1]), "r"(a[mt][2]), "r"(a[mt][3]),
                          "r"(b[nt][0]), "r"(b[nt][1]));
        }

        if (t + 1 < nk) {
            store_tile(buf ^ 1);
            __syncthreads();
        }
    }

    // epilogue: scale by dinv[row], store half2
#pragma unroll
    for (int mt = 0; mt < 2; mt++) {
        int r0 = row0 + wm * 32 + mt * 16 + gid;
        int r1 = r0 + 8;
        float dv0 = (r0 < M) ? dinv[r0] : 0.f;
        float dv1 = (r1 < M) ? dinv[r1] : 0.f;
#pragma unroll
        for (int nt = 0; nt < 4; nt++) {
            int cc = ocol0 + wn * 32 + nt * 8 + 2 * q;
            if (r0 < M)
                *(__half2*)(Ct + (size_t)r0 * ldc + cc) =
                    __floats2half2_rn(c[mt][nt][0] * dv0, c[mt][nt][1] * dv0);
            if (r1 < M)
                *(__half2*)(Ct + (size_t)r1 * ldc + cc) =
                    __floats2half2_rn(c[mt][nt][2] * dv1, c[mt][nt][3] * dv1);
        }
    }
}

// ---- fp16 accumulate helpers ----
__device__ __forceinline__ void hacc8(float* a, uint4 u) {
    const __half2* hp = (const __half2*)&u;
#pragma unroll
    for (int i = 0; i < 4; i++) {
        float2 f = __half22float2(hp[i]);
        a[2 * i] += f.x;
        a[2 * i + 1] += f.y;
    }
}
__device__ __forceinline__ void hacc4(float* a, uint2 u) {
    const __half2* hp = (const __half2*)&u;
#pragma unroll
    for (int i = 0; i < 2; i++) {
        float2 f = __half22float2(hp[i]);
        a[2 * i] += f.x;
        a[2 * i + 1] += f.y;
    }
}

// ---------------- gather layer 1 ----------------
__global__ __launch_bounds__(256) void gather1(const float* __restrict__ b1, int M)
{
    int w = (blockIdx.x * blockDim.x + threadIdx.x) >> 5;
    if (w >= M) return;
    int lane = threadIdx.x & 31;
    int base = g_rowptr[w];
    int deg = g_cnt[w];

    float a[8];
    {
        uint4 u = ((const uint4*)(g_t1h + (size_t)w * C1))[lane];
#pragma unroll
        for (int i = 0; i < 8; i++) a[i] = 0.f;
        hacc8(a, u);
    }

    for (int j = 0; j < deg; j += 32) {
        int nrem = min(32, deg - j);
        int idx = (j + lane < deg) ? g_srclist[base + j + lane] : 0;
        int k = 0;
        for (; k + 3 < nrem; k += 4) {
            int s0 = __shfl_sync(0xffffffff, idx, k);
            int s1 = __shfl_sync(0xffffffff, idx, k + 1);
            int s2 = __shfl_sync(0xffffffff, idx, k + 2);
            int s3 = __shfl_sync(0xffffffff, idx, k + 3);
            uint4 u0 = ((const uint4*)(g_t1h + (size_t)s0 * C1))[lane];
            uint4 u1 = ((const uint4*)(g_t1h + (size_t)s1 * C1))[lane];
            uint4 u2 = ((const uint4*)(g_t1h + (size_t)s2 * C1))[lane];
            uint4 u3 = ((const uint4*)(g_t1h + (size_t)s3 * C1))[lane];
            hacc8(a, u0); hacc8(a, u1); hacc8(a, u2); hacc8(a, u3);
        }
        for (; k < nrem; k++) {
            int s0 = __shfl_sync(0xffffffff, idx, k);
            hacc8(a, ((const uint4*)(g_t1h + (size_t)s0 * C1))[lane]);
        }
    }

    float dv = g_dinv[w];
    float4 bb0 = ((const float4*)b1)[lane * 2];
    float4 bb1 = ((const float4*)b1)[lane * 2 + 1];
    float4 o0, o1;
    o0.x = fmaxf(fmaf(dv, a[0], bb0.x), 0.f);
    o0.y = fmaxf(fmaf(dv, a[1], bb0.y), 0.f);
    o0.z = fmaxf(fmaf(dv, a[2], bb0.z), 0.f);
    o0.w = fmaxf(fmaf(dv, a[3], bb0.w), 0.f);
    o1.x = fmaxf(fmaf(dv, a[4], bb1.x), 0.f);
    o1.y = fmaxf(fmaf(dv, a[5], bb1.y), 0.f);
    o1.z = fmaxf(fmaf(dv, a[6], bb1.z), 0.f);
    o1.w = fmaxf(fmaf(dv, a[7], bb1.w), 0.f);
    float4* hp = (float4*)(g_h + (size_t)w * C1 + lane * 8);
    hp[0] = o0;
    hp[1] = o1;
}

// ---------------- gather layer 2 ----------------
__global__ __launch_bounds__(256) void gather2(int M)
{
    int w = (blockIdx.x * blockDim.x + threadIdx.x) >> 5;
    if (w >= M) return;
    int lane = threadIdx.x & 31;
    int base = g_rowptr[w];
    int deg = g_cnt[w];

    float a[4] = {0.f, 0.f, 0.f, 0.f};
    hacc4(a, ((const uint2*)(g_t2h + (size_t)w * C2))[lane]);

    for (int j = 0; j < deg; j += 32) {
        int nrem = min(32, deg - j);
        int idx = (j + lane < deg) ? g_srclist[base + j + lane] : 0;
        int k = 0;
        for (; k + 3 < nrem; k += 4) {
            int s0 = __shfl_sync(0xffffffff, idx, k);
            int s1 = __shfl_sync(0xffffffff, idx, k + 1);
            int s2 = __shfl_sync(0xffffffff, idx, k + 2);
            int s3 = __shfl_sync(0xffffffff, idx, k + 3);
            uint2 u0 = ((const uint2*)(g_t2h + (size_t)s0 * C2))[lane];
            uint2 u1 = ((const uint2*)(g_t2h + (size_t)s1 * C2))[lane];
            uint2 u2 = ((const uint2*)(g_t2h + (size_t)s2 * C2))[lane];
            uint2 u3 = ((const uint2*)(g_t2h + (size_t)s3 * C2))[lane];
            hacc4(a, u0); hacc4(a, u1); hacc4(a, u2); hacc4(a, u3);
        }
        for (; k < nrem; k++) {
            int s0 = __shfl_sync(0xffffffff, idx, k);
            hacc4(a, ((const uint2*)(g_t2h + (size_t)s0 * C2))[lane]);
        }
    }
    *(float4*)(g_acc2 + (size_t)w * C2 + lane * 4) = make_float4(a[0], a[1], a[2], a[3]);
}

// ---------------- head ----------------
__global__ __launch_bounds__(256) void head_kernel(
    const float* __restrict__ b_mu, const float* __restrict__ b_lv,
    const float* __restrict__ W_c, const float* __restrict__ b_c,
    const float* __restrict__ eps,
    float* __restrict__ out, int M)
{
    __shared__ float Wc[64 * 64];
    __shared__ float zs[4][64];
    int tid = threadIdx.x;
    for (int i = tid; i < 64 * 64; i += 256) Wc[i] = W_c[i];

    int c = tid & 63;
    int sub = tid >> 6;
    int n = blockIdx.x * 4 + sub;
    size_t MO = (size_t)M * 64;

    if (n < M) {
        float dv = g_dinv[n];
        float mu = fmaf(dv, g_acc2[(size_t)n * C2 + c], b_mu[c]);
        float lv = fmaf(dv, g_acc2[(size_t)n * C2 + 64 + c], b_lv[c]);
        float z = fmaf(eps[(size_t)n * 64 + c], __expf(0.5f * lv), mu);
        out[MO + (size_t)n * 64 + c] = mu;
        out[2 * MO + (size_t)n * 64 + c] = lv;
        zs[sub][c] = z;
    }
    __syncthreads();
    if (n < M) {
        float s = b_c[c];
#pragma unroll
        for (int k = 0; k < 64; k++) s = fmaf(zs[sub][k], Wc[k * 64 + c], s);
        out[(size_t)n * 64 + c] = s;
    }
}

extern "C" void kernel_launch(void* const* d_in, const int* in_sizes, int n_in,
                              void* d_out, int out_size) {
    const float* x    = (const float*)d_in[0];
    const int*   ei   = (const int*)d_in[1];
    const float* W1   = (const float*)d_in[2];
    const float* b1   = (const float*)d_in[3];
    const float* W_mu = (const float*)d_in[4];
    const float* b_mu = (const float*)d_in[5];
    const float* W_lv = (const float*)d_in[6];
    const float* b_lv = (const float*)d_in[7];
    const float* W_c  = (const float*)d_in[8];
    const float* b_c  = (const float*)d_in[9];
    const float* eps  = (const float*)d_in[10];
    float* out = (float*)d_out;

    const int M = in_sizes[0] / 512;   // 100000
    const int E = in_sizes[1] / 2;     // 3200000

    float *dinv, *h;
    __half *t1h, *t2h;
    cudaGetSymbolAddress((void**)&dinv, g_dinv);
    cudaGetSymbolAddress((void**)&t1h,  g_t1h);
    cudaGetSymbolAddress((void**)&h,    g_h);
    cudaGetSymbolAddress((void**)&t2h,  g_t2h);

    // ---- CSR build + dinv (5 launches; launch #5 = gemm1 for ncu -s 5) ----
    zero_cnt<<<(M + 255) / 256, 256>>>(M);
    count_deg<<<(E + 511) / 512, 512>>>(ei, E);
    scan_local<<<NBLK, SCAN_B>>>(M);
    scan_apply<<<(M + 255) / 256, 256>>>(M);
    fill_csr<<<(E + 511) / 512, 512>>>(ei, E);

    // ---- layer 1: t1h = dinv * (x @ W1)  [M x 256] ----
    {
        dim3 grid((M + TBM - 1) / TBM, C1 / TBN);
        gemm_h16<<<grid, 256>>>(x, 512, W1, W1, C1, C1 / TBN, t1h, C1, dinv, M, 512);
    }
    gather1<<<(M * 32 + 255) / 256, 256>>>(b1, M);

    // ---- layer 2 (one launch, grid.y picks W_mu / W_lv) ----
    {
        dim3 grid((M + TBM - 1) / TBM, 2);
        gemm_h16<<<grid, 256>>>(h, C1, W_mu, W_lv, 64, 1, t2h, C2, dinv, M, C1);
    }
    gather2<<<(M * 32 + 255) / 256, 256>>>(M);

    // ---- head ----
    head_kernel<<<(M + 3) / 4, 256>>>(b_mu, b_lv, W_c, b_c, eps, out, M);
}

// round 8
// speedup vs baseline: 6.6963x; 1.0440x over previous
#include <cuda_runtime.h>
#include <cuda_fp16.h>
#include <cstddef>
#include <cstdint>

#define NNODES 100000
#define NEDGES 3200000
#define C1 256
#define C2 128
#define SCAN_B 1024
#define NBLK ((NNODES + SCAN_B - 1) / SCAN_B)   // 98

// ---- scratch (static device globals) ----
__device__ int g_cnt   [NNODES];
__device__ int g_rowptr[NNODES];
__device__ int g_cursor[NNODES];
__device__ int g_bsum  [NBLK];
__device__ int g_srclist[NEDGES];
__device__ __align__(16) float  g_dinv[NNODES];
__device__ __align__(16) __half g_t1h[(size_t)NNODES * C1];  // UNscaled fp16 x@W1
__device__ __align__(16) __half g_hh [(size_t)NNODES * C1];  // fp16 hidden
__device__ __align__(16) __half g_t2h[(size_t)NNODES * C2];  // dinv-scaled fp16 h@[Wmu|Wlv]
__device__ __align__(16) float  g_acc2[(size_t)NNODES * C2];

// ---------------- CSR build ----------------
__global__ void zero_cnt(int M) {
    int i = blockIdx.x * blockDim.x + threadIdx.x;
    if (i < M) g_cnt[i] = 0;
}
__global__ void count_deg(const int* __restrict__ ei, int E) {
    int e = blockIdx.x * blockDim.x + threadIdx.x;
    if (e < E) atomicAdd(&g_cnt[ei[(size_t)E + e]], 1);
}
__global__ __launch_bounds__(SCAN_B) void scan_local(int M) {
    __shared__ int sh[SCAN_B];
    int tid = threadIdx.x;
    int i = blockIdx.x * SCAN_B + tid;
    int v = (i < M) ? g_cnt[i] : 0;
    if (i < M) g_dinv[i] = rsqrtf((float)(v + 1));
    sh[tid] = v;
    __syncthreads();
#pragma unroll
    for (int off = 1; off < SCAN_B; off <<= 1) {
        int t = (tid >= off) ? sh[tid - off] : 0;
        __syncthreads();
        sh[tid] += t;
        __syncthreads();
    }
    if (i < M) g_rowptr[i] = sh[tid] - v;
    if (tid == SCAN_B - 1) g_bsum[blockIdx.x] = sh[tid];
}
__global__ void scan_apply(int M) {
    __shared__ int s_off;
    int seg = (blockIdx.x * 256) / SCAN_B;
    if (threadIdx.x < 32) {
        int acc = 0;
        for (int j = threadIdx.x; j < seg; j += 32) acc += g_bsum[j];
#pragma unroll
        for (int o = 16; o; o >>= 1) acc += __shfl_down_sync(0xffffffff, acc, o);
        if (threadIdx.x == 0) s_off = acc;
    }
    __syncthreads();
    int i = blockIdx.x * 256 + threadIdx.x;
    if (i < M) {
        int r = g_rowptr[i] + s_off;
        g_rowptr[i] = r;
        g_cursor[i] = r;
    }
}
__global__ void fill_csr(const int* __restrict__ ei, int E) {
    int e = blockIdx.x * blockDim.x + threadIdx.x;
    if (e < E) {
        int s = ei[e];
        int d = ei[(size_t)E + e];
        int pos = atomicAdd(&g_cursor[d], 1);
        g_srclist[pos] = s;
    }
}

// ---------------- fp16 MMA GEMM with ldmatrix (A fp32 or fp16) ----------------
#define TBM 128
#define TBN 64
#define TBK 32
#define AST 40
#define BST 72

__device__ __forceinline__ void ldsm_x4(uint32_t& r0, uint32_t& r1, uint32_t& r2, uint32_t& r3,
                                        const void* p) {
    uint32_t addr = (uint32_t)__cvta_generic_to_shared(p);
    asm volatile("ldmatrix.sync.aligned.m8n8.x4.shared.b16 {%0,%1,%2,%3}, [%4];"
                 : "=r"(r0), "=r"(r1), "=r"(r2), "=r"(r3) : "r"(addr));
}
__device__ __forceinline__ void ldsm_x2t(uint32_t& r0, uint32_t& r1, const void* p) {
    uint32_t addr = (uint32_t)__cvta_generic_to_shared(p);
    asm volatile("ldmatrix.sync.aligned.m8n8.x2.trans.shared.b16 {%0,%1}, [%2];"
                 : "=r"(r0), "=r"(r1) : "r"(addr));
}

template <bool AHALF>
__global__ __launch_bounds__(256) void gemm_h16(
    const void* __restrict__ Ap, int lda,
    const float* __restrict__ B1, const float* __restrict__ B2,
    int ldb, int nby1,
    __half* __restrict__ Ct, int ldc,
    const float* __restrict__ dinv, int M, int K)
{
    __shared__ __align__(16) __half As[2][TBM][AST];
    __shared__ __align__(16) __half Bs[2][TBK][BST];

    const int tid = threadIdx.x;
    const int lane = tid & 31;
    const int warp = tid >> 5;
    const int wm = warp & 3;
    const int wn = warp >> 2;
    const int gid = lane >> 2;
    const int q = lane & 3;
    const int row0 = blockIdx.x * TBM;

    const float* B = (blockIdx.y < nby1) ? B1 : B2;
    const int bcol0 = (blockIdx.y < nby1) ? blockIdx.y * TBN
                                          : (blockIdx.y - nby1) * TBN;
    const int ocol0 = blockIdx.y * TBN;

    float c[2][4][4];
#pragma unroll
    for (int mt = 0; mt < 2; mt++)
#pragma unroll
        for (int nt = 0; nt < 4; nt++)
#pragma unroll
            for (int r = 0; r < 4; r++) c[mt][nt][r] = 0.f;

    const int nk = K / TBK;
    float4 Av[4];   // fp32 A regs
    uint4  Ah[2];   // fp16 A regs
    float4 Bv[2];

    auto load_tile = [&](int t) {
        int k0 = t * TBK;
        if (AHALF) {
            const __half* A = (const __half*)Ap;
#pragma unroll
            for (int i = 0; i < 2; i++) {
                int idx = tid + i * 256;           // uint4 id over 512
                int r = idx >> 2;                  // 4 uint4 per row
                int c8 = (idx & 3) << 3;
                int gr = row0 + r;
                Ah[i] = (gr < M) ? *(const uint4*)(A + (size_t)gr * lda + k0 + c8)
                                 : make_uint4(0, 0, 0, 0);
            }
        } else {
            const float* A = (const float*)Ap;
#pragma unroll
            for (int i = 0; i < 4; i++) {
                int idx = tid + i * 256;
                int r = idx >> 3;
                int c4 = (idx & 7) << 2;
                int gr = row0 + r;
                Av[i] = (gr < M) ? *(const float4*)(A + (size_t)gr * lda + k0 + c4)
                                 : make_float4(0.f, 0.f, 0.f, 0.f);
            }
        }
#pragma unroll
        for (int i = 0; i < 2; i++) {
            int idx = tid + i * 256;
            int r = idx >> 4;
            int c4 = (idx & 15) << 2;
            Bv[i] = *(const float4*)(B + (size_t)(k0 + r) * ldb + bcol0 + c4);
        }
    };
    auto store_tile = [&](int buf) {
        if (AHALF) {
#pragma unroll
            for (int i = 0; i < 2; i++) {
                int idx = tid + i * 256;
                int r = idx >> 2;
                int c8 = (idx & 3) << 3;
                *(uint4*)&As[buf][r][c8] = Ah[i];   // 80B row stride is 16B aligned
            }
        } else {
#pragma unroll
            for (int i = 0; i < 4; i++) {
                int idx = tid + i * 256;
                int r = idx >> 3;
                int c4 = (idx & 7) << 2;
                __half2 h01 = __floats2half2_rn(Av[i].x, Av[i].y);
                __half2 h23 = __floats2half2_rn(Av[i].z, Av[i].w);
                uint2 u = make_uint2(*(uint32_t*)&h01, *(uint32_t*)&h23);
                *(uint2*)&As[buf][r][c4] = u;
            }
        }
#pragma unroll
        for (int i = 0; i < 2; i++) {
            int idx = tid + i * 256;
            int r = idx >> 4;
            int c4 = (idx & 15) << 2;
            __half2 h01 = __floats2half2_rn(Bv[i].x, Bv[i].y);
            __half2 h23 = __floats2half2_rn(Bv[i].z, Bv[i].w);
            uint2 u = make_uint2(*(uint32_t*)&h01, *(uint32_t*)&h23);
            *(uint2*)&Bs[buf][r][c4] = u;
        }
    };

    load_tile(0);
    store_tile(0);
    __syncthreads();

    const int a_row = (lane & 15);
    const int a_koff = (lane >> 4) << 3;
    const int b_krow = (lane & 15);

    for (int t = 0; t < nk; t++) {
        int buf = t & 1;
        if (t + 1 < nk) load_tile(t + 1);

#pragma unroll
        for (int ks = 0; ks < TBK / 16; ks++) {
            int kb = ks * 16;
            uint32_t a[2][4], b[4][2];
#pragma unroll
            for (int mt = 0; mt < 2; mt++) {
                const __half* p = &As[buf][wm * 32 + mt * 16 + a_row][kb + a_koff];
                ldsm_x4(a[mt][0], a[mt][1], a[mt][2], a[mt][3], p);
            }
#pragma unroll
            for (int nt = 0; nt < 4; nt++) {
                const __half* p = &Bs[buf][kb + b_krow][wn * 32 + nt * 8];
                ldsm_x2t(b[nt][0], b[nt][1], p);
            }
#pragma unroll
            for (int mt = 0; mt < 2; mt++)
#pragma unroll
                for (int nt = 0; nt < 4; nt++)
                    asm volatile(
                        "mma.sync.aligned.m16n8k16.row.col.f32.f16.f16.f32 "
                        "{%0,%1,%2,%3}, {%4,%5,%6,%7}, {%8,%9}, {%0,%1,%2,%3};"
                        : "+f"(c[mt][nt][0]), "+f"(c[mt][nt][1]),
                          "+f"(c[mt][nt][2]), "+f"(c[mt][nt][3])
                        : "r"(a[mt][0]), "r"(a[mt][1]), "r"(a[mt][2]), "r"(a[mt][3]),
                          "r"(b[nt][0]), "r"(b[nt][1]));
        }

        if (t + 1 < nk) {
            store_tile(buf ^ 1);
            __syncthreads();
        }
    }

#pragma unroll
    for (int mt = 0; mt < 2; mt++) {
        int r0 = row0 + wm * 32 + mt * 16 + gid;
        int r1 = r0 + 8;
        float dv0 = 1.f, dv1 = 1.f;
        if (dinv) {
            dv0 = (r0 < M) ? dinv[r0] : 0.f;
            dv1 = (r1 < M) ? dinv[r1] : 0.f;
        }
#pragma unroll
        for (int nt = 0; nt < 4; nt++) {
            int cc = ocol0 + wn * 32 + nt * 8 + 2 * q;
            if (r0 < M)
                *(__half2*)(Ct + (size_t)r0 * ldc + cc) =
                    __floats2half2_rn(c[mt][nt][0] * dv0, c[mt][nt][1] * dv0);
            if (r1 < M)
                *(__half2*)(Ct + (size_t)r1 * ldc + cc) =
                    __floats2half2_rn(c[mt][nt][2] * dv1, c[mt][nt][3] * dv1);
        }
    }
}

// ---- fp16 accumulate helpers ----
__device__ __forceinline__ void hacc8s(float* a, uint4 u, float dv) {
    const __half2* hp = (const __half2*)&u;
#pragma unroll
    for (int i = 0; i < 4; i++) {
        float2 f = __half22float2(hp[i]);
        a[2 * i]     = fmaf(dv, f.x, a[2 * i]);
        a[2 * i + 1] = fmaf(dv, f.y, a[2 * i + 1]);
    }
}
__device__ __forceinline__ void hacc4(float* a, uint2 u) {
    const __half2* hp = (const __half2*)&u;
#pragma unroll
    for (int i = 0; i < 2; i++) {
        float2 f = __half22float2(hp[i]);
        a[2 * i] += f.x;
        a[2 * i + 1] += f.y;
    }
}

// ---------------- gather layer 1: h = relu(dinv[w]*(Σ dinv[s]*t1[s] + dinv[w]*t1[w]) + b1) ----------------
__global__ __launch_bounds__(256) void gather1(const float* __restrict__ b1, int M)
{
    int w = (blockIdx.x * blockDim.x + threadIdx.x) >> 5;
    if (w >= M) return;
    int lane = threadIdx.x & 31;
    int base = g_rowptr[w];
    int deg = g_cnt[w];
    float dvw = g_dinv[w];

    float a[8];
#pragma unroll
    for (int i = 0; i < 8; i++) a[i] = 0.f;
    hacc8s(a, ((const uint4*)(g_t1h + (size_t)w * C1))[lane], dvw);  // self

    for (int j = 0; j < deg; j += 32) {
        int nrem = min(32, deg - j);
        int valid = (j + lane < deg);
        int idx = valid ? g_srclist[base + j + lane] : 0;
        float dvl = valid ? g_dinv[idx] : 0.f;
        int k = 0;
        for (; k + 3 < nrem; k += 4) {
            int s0 = __shfl_sync(0xffffffff, idx, k);
            int s1 = __shfl_sync(0xffffffff, idx, k + 1);
            int s2 = __shfl_sync(0xffffffff, idx, k + 2);
            int s3 = __shfl_sync(0xffffffff, idx, k + 3);
            float d0 = __shfl_sync(0xffffffff, dvl, k);
            float d1 = __shfl_sync(0xffffffff, dvl, k + 1);
            float d2 = __shfl_sync(0xffffffff, dvl, k + 2);
            float d3 = __shfl_sync(0xffffffff, dvl, k + 3);
            uint4 u0 = ((const uint4*)(g_t1h + (size_t)s0 * C1))[lane];
            uint4 u1 = ((const uint4*)(g_t1h + (size_t)s1 * C1))[lane];
            uint4 u2 = ((const uint4*)(g_t1h + (size_t)s2 * C1))[lane];
            uint4 u3 = ((const uint4*)(g_t1h + (size_t)s3 * C1))[lane];
            hacc8s(a, u0, d0); hacc8s(a, u1, d1); hacc8s(a, u2, d2); hacc8s(a, u3, d3);
        }
        for (; k < nrem; k++) {
            int s0 = __shfl_sync(0xffffffff, idx, k);
            float d0 = __shfl_sync(0xffffffff, dvl, k);
            hacc8s(a, ((const uint4*)(g_t1h + (size_t)s0 * C1))[lane], d0);
        }
    }

    float4 bb0 = ((const float4*)b1)[lane * 2];
    float4 bb1 = ((const float4*)b1)[lane * 2 + 1];
    float o[8];
    o[0] = fmaxf(fmaf(dvw, a[0], bb0.x), 0.f);
    o[1] = fmaxf(fmaf(dvw, a[1], bb0.y), 0.f);
    o[2] = fmaxf(fmaf(dvw, a[2], bb0.z), 0.f);
    o[3] = fmaxf(fmaf(dvw, a[3], bb0.w), 0.f);
    o[4] = fmaxf(fmaf(dvw, a[4], bb1.x), 0.f);
    o[5] = fmaxf(fmaf(dvw, a[5], bb1.y), 0.f);
    o[6] = fmaxf(fmaf(dvw, a[6], bb1.z), 0.f);
    o[7] = fmaxf(fmaf(dvw, a[7], bb1.w), 0.f);
    __half2 h0 = __floats2half2_rn(o[0], o[1]);
    __half2 h1 = __floats2half2_rn(o[2], o[3]);
    __half2 h2 = __floats2half2_rn(o[4], o[5]);
    __half2 h3 = __floats2half2_rn(o[6], o[7]);
    uint4 u = make_uint4(*(uint32_t*)&h0, *(uint32_t*)&h1, *(uint32_t*)&h2, *(uint32_t*)&h3);
    ((uint4*)(g_hh + (size_t)w * C1))[lane] = u;
}

// ---------------- gather layer 2: acc2 = self + sum t2h[src]  (t2h pre-scaled by dinv) ----------------
__global__ __launch_bounds__(256) void gather2(int M)
{
    int w = (blockIdx.x * blockDim.x + threadIdx.x) >> 5;
    if (w >= M) return;
    int lane = threadIdx.x & 31;
    int base = g_rowptr[w];
    int deg = g_cnt[w];

    float a[4] = {0.f, 0.f, 0.f, 0.f};
    hacc4(a, ((const uint2*)(g_t2h + (size_t)w * C2))[lane]);

    for (int j = 0; j < deg; j += 32) {
        int nrem = min(32, deg - j);
        int idx = (j + lane < deg) ? g_srclist[base + j + lane] : 0;
        int k = 0;
        for (; k + 3 < nrem; k += 4) {
            int s0 = __shfl_sync(0xffffffff, idx, k);
            int s1 = __shfl_sync(0xffffffff, idx, k + 1);
            int s2 = __shfl_sync(0xffffffff, idx, k + 2);
            int s3 = __shfl_sync(0xffffffff, idx, k + 3);
            uint2 u0 = ((const uint2*)(g_t2h + (size_t)s0 * C2))[lane];
            uint2 u1 = ((const uint2*)(g_t2h + (size_t)s1 * C2))[lane];
            uint2 u2 = ((const uint2*)(g_t2h + (size_t)s2 * C2))[lane];
            uint2 u3 = ((const uint2*)(g_t2h + (size_t)s3 * C2))[lane];
            hacc4(a, u0); hacc4(a, u1); hacc4(a, u2); hacc4(a, u3);
        }
        for (; k < nrem; k++) {
            int s0 = __shfl_sync(0xffffffff, idx, k);
            hacc4(a, ((const uint2*)(g_t2h + (size_t)s0 * C2))[lane]);
        }
    }
    *(float4*)(g_acc2 + (size_t)w * C2 + lane * 4) = make_float4(a[0], a[1], a[2], a[3]);
}

// ---------------- head ----------------
__global__ __launch_bounds__(256) void head_kernel(
    const float* __restrict__ b_mu, const float* __restrict__ b_lv,
    const float* __restrict__ W_c, const float* __restrict__ b_c,
    const float* __restrict__ eps,
    float* __restrict__ out, int M)
{
    __shared__ float Wc[64 * 64];
    __shared__ float zs[4][64];
    int tid = threadIdx.x;
    for (int i = tid; i < 64 * 64; i += 256) Wc[i] = W_c[i];

    int c = tid & 63;
    int sub = tid >> 6;
    int n = blockIdx.x * 4 + sub;
    size_t MO = (size_t)M * 64;

    if (n < M) {
        float dv = g_dinv[n];
        float mu = fmaf(dv, g_acc2[(size_t)n * C2 + c], b_mu[c]);
        float lv = fmaf(dv, g_acc2[(size_t)n * C2 + 64 + c], b_lv[c]);
        float z = fmaf(eps[(size_t)n * 64 + c], __expf(0.5f * lv), mu);
        out[MO + (size_t)n * 64 + c] = mu;
        out[2 * MO + (size_t)n * 64 + c] = lv;
        zs[sub][c] = z;
    }
    __syncthreads();
    if (n < M) {
        float s = b_c[c];
#pragma unroll
        for (int k = 0; k < 64; k++) s = fmaf(zs[sub][k], Wc[k * 64 + c], s);
        out[(size_t)n * 64 + c] = s;
    }
}

extern "C" void kernel_launch(void* const* d_in, const int* in_sizes, int n_in,
                              void* d_out, int out_size) {
    const float* x    = (const float*)d_in[0];
    const int*   ei   = (const int*)d_in[1];
    const float* W1   = (const float*)d_in[2];
    const float* b1   = (const float*)d_in[3];
    const float* W_mu = (const float*)d_in[4];
    const float* b_mu = (const float*)d_in[5];
    const float* W_lv = (const float*)d_in[6];
    const float* b_lv = (const float*)d_in[7];
    const float* W_c  = (const float*)d_in[8];
    const float* b_c  = (const float*)d_in[9];
    const float* eps  = (const float*)d_in[10];
    float* out = (float*)d_out;

    const int M = in_sizes[0] / 512;   // 100000
    const int E = in_sizes[1] / 2;     // 3200000

    float* dinv;
    __half *t1h, *hh, *t2h;
    cudaGetSymbolAddress((void**)&dinv, g_dinv);
    cudaGetSymbolAddress((void**)&t1h,  g_t1h);
    cudaGetSymbolAddress((void**)&hh,   g_hh);
    cudaGetSymbolAddress((void**)&t2h,  g_t2h);

    // one-time side stream + events (host-side handles only; graph content identical every call)
    static cudaStream_t s2 = nullptr;
    static cudaEvent_t ev_fork = nullptr, ev_join = nullptr;
    if (!s2) {
        cudaStreamCreateWithFlags(&s2, cudaStreamNonBlocking);
        cudaEventCreateWithFlags(&ev_fork, cudaEventDisableTiming);
        cudaEventCreateWithFlags(&ev_join, cudaEventDisableTiming);
    }

    // ---- fork: CSR build chain on s2, GEMM1 on main ----
    cudaEventRecord(ev_fork, 0);
    cudaStreamWaitEvent(s2, ev_fork, 0);

    zero_cnt  <<<(M + 255) / 256, 256, 0, s2>>>(M);
    count_deg <<<(E + 511) / 512, 512, 0, s2>>>(ei, E);
    scan_local<<<NBLK, SCAN_B, 0, s2>>>(M);
    scan_apply<<<(M + 255) / 256, 256, 0, s2>>>(M);
    fill_csr  <<<(E + 511) / 512, 512, 0, s2>>>(ei, E);
    cudaEventRecord(ev_join, s2);

    // GEMM1 (no dinv dependency): t1h = fp16(x @ W1)
    {
        dim3 grid((M + TBM - 1) / TBM, C1 / TBN);
        gemm_h16<false><<<grid, 256>>>(x, 512, W1, W1, C1, C1 / TBN,
                                       t1h, C1, nullptr, M, 512);
    }

    // ---- join, then rest of pipeline ----
    cudaStreamWaitEvent(0, ev_join, 0);
    gather1<<<(M * 32 + 255) / 256, 256>>>(b1, M);

    {
        dim3 grid((M + TBM - 1) / TBM, 2);
        gemm_h16<true><<<grid, 256>>>(hh, C1, W_mu, W_lv, 64, 1,
                                      t2h, C2, dinv, M, C1);
    }
    gather2<<<(M * 32 + 255) / 256, 256>>>(M);

    head_kernel<<<(M + 3) / 4, 256>>>(b_mu, b_lv, W_c, b_c, eps, out, M);
}

// round 9
// speedup vs baseline: 7.4732x; 1.1160x over previous
#include <cuda_runtime.h>
#include <cuda_fp16.h>
#include <cstddef>
#include <cstdint>

#define NNODES 100000
#define NEDGES 3200000
#define C1 256
#define C2 128
#define SCAN_B 1024
#define NBLK ((NNODES + SCAN_B - 1) / SCAN_B)   // 98

// ---- scratch (static device globals) ----
__device__ int g_cnt   [NNODES];
__device__ int g_rowptr[NNODES];
__device__ int g_cursor[NNODES];
__device__ int g_bsum  [NBLK];
__device__ int g_srclist[NEDGES];
__device__ __align__(16) float  g_dinv[NNODES];
__device__ __align__(16) __half g_t1h[(size_t)NNODES * C1];  // UNscaled fp16 x@W1
__device__ __align__(16) __half g_hh [(size_t)NNODES * C1];  // fp16 hidden
__device__ __align__(16) __half g_t2h[(size_t)NNODES * C2];  // dinv-scaled fp16 h@[Wmu|Wlv]

// ---------------- CSR build ----------------
__global__ void zero_cnt(int M) {
    int i = blockIdx.x * blockDim.x + threadIdx.x;
    if (i < M) g_cnt[i] = 0;
}
__global__ void count_deg(const int* __restrict__ ei, int E) {
    int e = blockIdx.x * blockDim.x + threadIdx.x;
    if (e < E) atomicAdd(&g_cnt[ei[(size_t)E + e]], 1);
}
__global__ __launch_bounds__(SCAN_B) void scan_local(int M) {
    __shared__ int sh[SCAN_B];
    int tid = threadIdx.x;
    int i = blockIdx.x * SCAN_B + tid;
    int v = (i < M) ? g_cnt[i] : 0;
    if (i < M) g_dinv[i] = rsqrtf((float)(v + 1));
    sh[tid] = v;
    __syncthreads();
#pragma unroll
    for (int off = 1; off < SCAN_B; off <<= 1) {
        int t = (tid >= off) ? sh[tid - off] : 0;
        __syncthreads();
        sh[tid] += t;
        __syncthreads();
    }
    if (i < M) g_rowptr[i] = sh[tid] - v;
    if (tid == SCAN_B - 1) g_bsum[blockIdx.x] = sh[tid];
}
__global__ void scan_apply(int M) {
    __shared__ int s_off;
    int seg = (blockIdx.x * 256) / SCAN_B;
    if (threadIdx.x < 32) {
        int acc = 0;
        for (int j = threadIdx.x; j < seg; j += 32) acc += g_bsum[j];
#pragma unroll
        for (int o = 16; o; o >>= 1) acc += __shfl_down_sync(0xffffffff, acc, o);
        if (threadIdx.x == 0) s_off = acc;
    }
    __syncthreads();
    int i = blockIdx.x * 256 + threadIdx.x;
    if (i < M) {
        int r = g_rowptr[i] + s_off;
        g_rowptr[i] = r;
        g_cursor[i] = r;
    }
}
__global__ void fill_csr(const int* __restrict__ ei, int E) {
    int e = blockIdx.x * blockDim.x + threadIdx.x;
    if (e < E) {
        int s = ei[e];
        int d = ei[(size_t)E + e];
        int pos = atomicAdd(&g_cursor[d], 1);
        g_srclist[pos] = s;
    }
}

// ---------------- fp16 MMA GEMM with ldmatrix (A fp32 or fp16) ----------------
// 1-D grid, block swizzle: by = id % nby (column tiles adjacent -> share A via L2)
#define TBM 128
#define TBN 64
#define TBK 32
#define AST 40
#define BST 72

__device__ __forceinline__ void ldsm_x4(uint32_t& r0, uint32_t& r1, uint32_t& r2, uint32_t& r3,
                                        const void* p) {
    uint32_t addr = (uint32_t)__cvta_generic_to_shared(p);
    asm volatile("ldmatrix.sync.aligned.m8n8.x4.shared.b16 {%0,%1,%2,%3}, [%4];"
                 : "=r"(r0), "=r"(r1), "=r"(r2), "=r"(r3) : "r"(addr));
}
__device__ __forceinline__ void ldsm_x2t(uint32_t& r0, uint32_t& r1, const void* p) {
    uint32_t addr = (uint32_t)__cvta_generic_to_shared(p);
    asm volatile("ldmatrix.sync.aligned.m8n8.x2.trans.shared.b16 {%0,%1}, [%2];"
                 : "=r"(r0), "=r"(r1) : "r"(addr));
}

template <bool AHALF>
__global__ __launch_bounds__(256) void gemm_h16(
    const void* __restrict__ Ap, int lda,
    const float* __restrict__ B1, const float* __restrict__ B2,
    int ldb, int nby, int nby1,
    __half* __restrict__ Ct, int ldc,
    const float* __restrict__ dinv, int M, int K)
{
    __shared__ __align__(16) __half As[2][TBM][AST];
    __shared__ __align__(16) __half Bs[2][TBK][BST];

    const int tid = threadIdx.x;
    const int lane = tid & 31;
    const int warp = tid >> 5;
    const int wm = warp & 3;
    const int wn = warp >> 2;
    const int gid = lane >> 2;
    const int q = lane & 3;

    const int by = blockIdx.x % nby;
    const int bx = blockIdx.x / nby;
    const int row0 = bx * TBM;

    const float* B = (by < nby1) ? B1 : B2;
    const int bcol0 = (by < nby1) ? by * TBN : (by - nby1) * TBN;
    const int ocol0 = by * TBN;

    float c[2][4][4];
#pragma unroll
    for (int mt = 0; mt < 2; mt++)
#pragma unroll
        for (int nt = 0; nt < 4; nt++)
#pragma unroll
            for (int r = 0; r < 4; r++) c[mt][nt][r] = 0.f;

    const int nk = K / TBK;
    float4 Av[4];
    uint4  Ah[2];
    float4 Bv[2];

    auto load_tile = [&](int t) {
        int k0 = t * TBK;
        if (AHALF) {
            const __half* A = (const __half*)Ap;
#pragma unroll
            for (int i = 0; i < 2; i++) {
                int idx = tid + i * 256;
                int r = idx >> 2;
                int c8 = (idx & 3) << 3;
                int gr = row0 + r;
                Ah[i] = (gr < M) ? *(const uint4*)(A + (size_t)gr * lda + k0 + c8)
                                 : make_uint4(0, 0, 0, 0);
            }
        } else {
            const float* A = (const float*)Ap;
#pragma unroll
            for (int i = 0; i < 4; i++) {
                int idx = tid + i * 256;
                int r = idx >> 3;
                int c4 = (idx & 7) << 2;
                int gr = row0 + r;
                Av[i] = (gr < M) ? *(const float4*)(A + (size_t)gr * lda + k0 + c4)
                                 : make_float4(0.f, 0.f, 0.f, 0.f);
            }
        }
#pragma unroll
        for (int i = 0; i < 2; i++) {
            int idx = tid + i * 256;
            int r = idx >> 4;
            int c4 = (idx & 15) << 2;
            Bv[i] = *(const float4*)(B + (size_t)(k0 + r) * ldb + bcol0 + c4);
        }
    };
    auto store_tile = [&](int buf) {
        if (AHALF) {
#pragma unroll
            for (int i = 0; i < 2; i++) {
                int idx = tid + i * 256;
                int r = idx >> 2;
                int c8 = (idx & 3) << 3;
                *(uint4*)&As[buf][r][c8] = Ah[i];
            }
        } else {
#pragma unroll
            for (int i = 0; i < 4; i++) {
                int idx = tid + i * 256;
                int r = idx >> 3;
                int c4 = (idx & 7) << 2;
                __half2 h01 = __floats2half2_rn(Av[i].x, Av[i].y);
                __half2 h23 = __floats2half2_rn(Av[i].z, Av[i].w);
                uint2 u = make_uint2(*(uint32_t*)&h01, *(uint32_t*)&h23);
                *(uint2*)&As[buf][r][c4] = u;
            }
        }
#pragma unroll
        for (int i = 0; i < 2; i++) {
            int idx = tid + i * 256;
            int r = idx >> 4;
            int c4 = (idx & 15) << 2;
            __half2 h01 = __floats2half2_rn(Bv[i].x, Bv[i].y);
            __half2 h23 = __floats2half2_rn(Bv[i].z, Bv[i].w);
            uint2 u = make_uint2(*(uint32_t*)&h01, *(uint32_t*)&h23);
            *(uint2*)&Bs[buf][r][c4] = u;
        }
    };

    load_tile(0);
    store_tile(0);
    __syncthreads();

    const int a_row = (lane & 15);
    const int a_koff = (lane >> 4) << 3;
    const int b_krow = (lane & 15);

    for (int t = 0; t < nk; t++) {
        int buf = t & 1;
        if (t + 1 < nk) load_tile(t + 1);

#pragma unroll
        for (int ks = 0; ks < TBK / 16; ks++) {
            int kb = ks * 16;
            uint32_t a[2][4], b[4][2];
#pragma unroll
            for (int mt = 0; mt < 2; mt++) {
                const __half* p = &As[buf][wm * 32 + mt * 16 + a_row][kb + a_koff];
                ldsm_x4(a[mt][0], a[mt][1], a[mt][2], a[mt][3], p);
            }
#pragma unroll
            for (int nt = 0; nt < 4; nt++) {
                const __half* p = &Bs[buf][kb + b_krow][wn * 32 + nt * 8];
                ldsm_x2t(b[nt][0], b[nt][1], p);
            }
#pragma unroll
            for (int mt = 0; mt < 2; mt++)
#pragma unroll
                for (int nt = 0; nt < 4; nt++)
                    asm volatile(
                        "mma.sync.aligned.m16n8k16.row.col.f32.f16.f16.f32 "
                        "{%0,%1,%2,%3}, {%4,%5,%6,%7}, {%8,%9}, {%0,%1,%2,%3};"
                        : "+f"(c[mt][nt][0]), "+f"(c[mt][nt][1]),
                          "+f"(c[mt][nt][2]), "+f"(c[mt][nt][3])
                        : "r"(a[mt][0]), "r"(a[mt][1]), "r"(a[mt][2]), "r"(a[mt][3]),
                          "r"(b[nt][0]), "r"(b[nt][1]));
        }

        if (t + 1 < nk) {
            store_tile(buf ^ 1);
            __syncthreads();
        }
    }

#pragma unroll
    for (int mt = 0; mt < 2; mt++) {
        int r0 = row0 + wm * 32 + mt * 16 + gid;
        int r1 = r0 + 8;
        float dv0 = 1.f, dv1 = 1.f;
        if (dinv) {
            dv0 = (r0 < M) ? dinv[r0] : 0.f;
            dv1 = (r1 < M) ? dinv[r1] : 0.f;
        }
#pragma unroll
        for (int nt = 0; nt < 4; nt++) {
            int cc = ocol0 + wn * 32 + nt * 8 + 2 * q;
            if (r0 < M)
                *(__half2*)(Ct + (size_t)r0 * ldc + cc) =
                    __floats2half2_rn(c[mt][nt][0] * dv0, c[mt][nt][1] * dv0);
            if (r1 < M)
                *(__half2*)(Ct + (size_t)r1 * ldc + cc) =
                    __floats2half2_rn(c[mt][nt][2] * dv1, c[mt][nt][3] * dv1);
        }
    }
}

// ---- fp16 accumulate helpers ----
__device__ __forceinline__ void hacc8s(float* a, uint4 u, float dv) {
    const __half2* hp = (const __half2*)&u;
#pragma unroll
    for (int i = 0; i < 4; i++) {
        float2 f = __half22float2(hp[i]);
        a[2 * i]     = fmaf(dv, f.x, a[2 * i]);
        a[2 * i + 1] = fmaf(dv, f.y, a[2 * i + 1]);
    }
}
__device__ __forceinline__ void hacc4(float* a, uint2 u) {
    const __half2* hp = (const __half2*)&u;
#pragma unroll
    for (int i = 0; i < 2; i++) {
        float2 f = __half22float2(hp[i]);
        a[2 * i] += f.x;
        a[2 * i + 1] += f.y;
    }
}

// ---------------- gather layer 1 ----------------
__global__ __launch_bounds__(256) void gather1(const float* __restrict__ b1, int M)
{
    int w = (blockIdx.x * blockDim.x + threadIdx.x) >> 5;
    if (w >= M) return;
    int lane = threadIdx.x & 31;
    int base = g_rowptr[w];
    int deg = g_cnt[w];
    float dvw = g_dinv[w];

    float a[8];
#pragma unroll
    for (int i = 0; i < 8; i++) a[i] = 0.f;
    hacc8s(a, ((const uint4*)(g_t1h + (size_t)w * C1))[lane], dvw);

    for (int j = 0; j < deg; j += 32) {
        int nrem = min(32, deg - j);
        int valid = (j + lane < deg);
        int idx = valid ? g_srclist[base + j + lane] : 0;
        float dvl = valid ? g_dinv[idx] : 0.f;
        int k = 0;
        for (; k + 3 < nrem; k += 4) {
            int s0 = __shfl_sync(0xffffffff, idx, k);
            int s1 = __shfl_sync(0xffffffff, idx, k + 1);
            int s2 = __shfl_sync(0xffffffff, idx, k + 2);
            int s3 = __shfl_sync(0xffffffff, idx, k + 3);
            float d0 = __shfl_sync(0xffffffff, dvl, k);
            float d1 = __shfl_sync(0xffffffff, dvl, k + 1);
            float d2 = __shfl_sync(0xffffffff, dvl, k + 2);
            float d3 = __shfl_sync(0xffffffff, dvl, k + 3);
            uint4 u0 = ((const uint4*)(g_t1h + (size_t)s0 * C1))[lane];
            uint4 u1 = ((const uint4*)(g_t1h + (size_t)s1 * C1))[lane];
            uint4 u2 = ((const uint4*)(g_t1h + (size_t)s2 * C1))[lane];
            uint4 u3 = ((const uint4*)(g_t1h + (size_t)s3 * C1))[lane];
            hacc8s(a, u0, d0); hacc8s(a, u1, d1); hacc8s(a, u2, d2); hacc8s(a, u3, d3);
        }
        for (; k < nrem; k++) {
            int s0 = __shfl_sync(0xffffffff, idx, k);
            float d0 = __shfl_sync(0xffffffff, dvl, k);
            hacc8s(a, ((const uint4*)(g_t1h + (size_t)s0 * C1))[lane], d0);
        }
    }

    float4 bb0 = ((const float4*)b1)[lane * 2];
    float4 bb1 = ((const float4*)b1)[lane * 2 + 1];
    float o[8];
    o[0] = fmaxf(fmaf(dvw, a[0], bb0.x), 0.f);
    o[1] = fmaxf(fmaf(dvw, a[1], bb0.y), 0.f);
    o[2] = fmaxf(fmaf(dvw, a[2], bb0.z), 0.f);
    o[3] = fmaxf(fmaf(dvw, a[3], bb0.w), 0.f);
    o[4] = fmaxf(fmaf(dvw, a[4], bb1.x), 0.f);
    o[5] = fmaxf(fmaf(dvw, a[5], bb1.y), 0.f);
    o[6] = fmaxf(fmaf(dvw, a[6], bb1.z), 0.f);
    o[7] = fmaxf(fmaf(dvw, a[7], bb1.w), 0.f);
    __half2 h0 = __floats2half2_rn(o[0], o[1]);
    __half2 h1 = __floats2half2_rn(o[2], o[3]);
    __half2 h2 = __floats2half2_rn(o[4], o[5]);
    __half2 h3 = __floats2half2_rn(o[6], o[7]);
    uint4 u = make_uint4(*(uint32_t*)&h0, *(uint32_t*)&h1, *(uint32_t*)&h2, *(uint32_t*)&h3);
    ((uint4*)(g_hh + (size_t)w * C1))[lane] = u;
}

// ---------------- fused gather2 + head ----------------
// warp per node: aggregate 128 ch (mu|lv), finalize, reparameterize, classify.
// lanes 0-15 hold mu channels (lane*4..+3), lanes 16-31 hold lv channels.
__global__ __launch_bounds__(256) void gather2_head(
    const float* __restrict__ b_mu, const float* __restrict__ b_lv,
    const float* __restrict__ W_c, const float* __restrict__ b_c,
    const float* __restrict__ eps,
    float* __restrict__ out, int M)
{
    __shared__ float sWc[64 * 64];    // 16KB
    __shared__ float sz[8][64];       // per-warp z staging
    int tid = threadIdx.x;
    for (int i = tid; i < 64 * 64; i += 256) sWc[i] = W_c[i];
    __syncthreads();

    int w = (blockIdx.x * blockDim.x + tid) >> 5;
    if (w >= M) return;
    int lane = tid & 31;
    int wid = (tid >> 5);
    int base = g_rowptr[w];
    int deg = g_cnt[w];

    float a[4] = {0.f, 0.f, 0.f, 0.f};
    hacc4(a, ((const uint2*)(g_t2h + (size_t)w * C2))[lane]);

    for (int j = 0; j < deg; j += 32) {
        int nrem = min(32, deg - j);
        int idx = (j + lane < deg) ? g_srclist[base + j + lane] : 0;
        int k = 0;
        for (; k + 3 < nrem; k += 4) {
            int s0 = __shfl_sync(0xffffffff, idx, k);
            int s1 = __shfl_sync(0xffffffff, idx, k + 1);
            int s2 = __shfl_sync(0xffffffff, idx, k + 2);
            int s3 = __shfl_sync(0xffffffff, idx, k + 3);
            uint2 u0 = ((const uint2*)(g_t2h + (size_t)s0 * C2))[lane];
            uint2 u1 = ((const uint2*)(g_t2h + (size_t)s1 * C2))[lane];
            uint2 u2 = ((const uint2*)(g_t2h + (size_t)s2 * C2))[lane];
            uint2 u3 = ((const uint2*)(g_t2h + (size_t)s3 * C2))[lane];
            hacc4(a, u0); hacc4(a, u1); hacc4(a, u2); hacc4(a, u3);
        }
        for (; k < nrem; k++) {
            int s0 = __shfl_sync(0xffffffff, idx, k);
            hacc4(a, ((const uint2*)(g_t2h + (size_t)s0 * C2))[lane]);
        }
    }

    // finalize: v = dv * a + bias   (mu lanes 0-15, lv lanes 16-31)
    float dv = g_dinv[w];
    bool is_mu = lane < 16;
    int cm = is_mu ? lane * 4 : (lane - 16) * 4;     // channel within 64
    float4 bb = is_mu ? ((const float4*)b_mu)[cm >> 2] : ((const float4*)b_lv)[cm >> 2];
    float v[4];
    v[0] = fmaf(dv, a[0], bb.x);
    v[1] = fmaf(dv, a[1], bb.y);
    v[2] = fmaf(dv, a[2], bb.z);
    v[3] = fmaf(dv, a[3], bb.w);

    size_t MO = (size_t)M * 64;
    // write mu / logvar (float4, coalesced within half-warp)
    float* dst = is_mu ? (out + MO + (size_t)w * 64 + cm)
                       : (out + 2 * MO + (size_t)w * 64 + cm);
    *(float4*)dst = make_float4(v[0], v[1], v[2], v[3]);

    // z = mu + eps * exp(0.5 * lv)  on mu lanes
    float lv0 = __shfl_sync(0xffffffff, v[0], lane + 16);
    float lv1 = __shfl_sync(0xffffffff, v[1], lane + 16);
    float lv2 = __shfl_sync(0xffffffff, v[2], lane + 16);
    float lv3 = __shfl_sync(0xffffffff, v[3], lane + 16);
    if (is_mu) {
        float4 ep = *(const float4*)(eps + (size_t)w * 64 + cm);
        sz[wid][cm + 0] = fmaf(ep.x, __expf(0.5f * lv0), v[0]);
        sz[wid][cm + 1] = fmaf(ep.y, __expf(0.5f * lv1), v[1]);
        sz[wid][cm + 2] = fmaf(ep.z, __expf(0.5f * lv2), v[2]);
        sz[wid][cm + 3] = fmaf(ep.w, __expf(0.5f * lv3), v[3]);
    }
    __syncwarp();

    // classifier: each lane computes out channels lane and lane+32
    float s1 = b_c[lane];
    float s2 = b_c[lane + 32];
#pragma unroll 16
    for (int c = 0; c < 64; c++) {
        float zc = sz[wid][c];
        s1 = fmaf(zc, sWc[c * 64 + lane], s1);
        s2 = fmaf(zc, sWc[c * 64 + lane + 32], s2);
    }
    out[(size_t)w * 64 + lane] = s1;
    out[(size_t)w * 64 + lane + 32] = s2;
}

extern "C" void kernel_launch(void* const* d_in, const int* in_sizes, int n_in,
                              void* d_out, int out_size) {
    const float* x    = (const float*)d_in[0];
    const int*   ei   = (const int*)d_in[1];
    const float* W1   = (const float*)d_in[2];
    const float* b1   = (const float*)d_in[3];
    const float* W_mu = (const float*)d_in[4];
    const float* b_mu = (const float*)d_in[5];
    const float* W_lv = (const float*)d_in[6];
    const float* b_lv = (const float*)d_in[7];
    const float* W_c  = (const float*)d_in[8];
    const float* b_c  = (const float*)d_in[9];
    const float* eps  = (const float*)d_in[10];
    float* out = (float*)d_out;

    const int M = in_sizes[0] / 512;   // 100000
    const int E = in_sizes[1] / 2;     // 3200000

    float* dinv;
    __half *t1h, *hh, *t2h;
    cudaGetSymbolAddress((void**)&dinv, g_dinv);
    cudaGetSymbolAddress((void**)&t1h,  g_t1h);
    cudaGetSymbolAddress((void**)&hh,   g_hh);
    cudaGetSymbolAddress((void**)&t2h,  g_t2h);

    static cudaStream_t s2 = nullptr;
    static cudaEvent_t ev_fork = nullptr, ev_join = nullptr;
    if (!s2) {
        cudaStreamCreateWithFlags(&s2, cudaStreamNonBlocking);
        cudaEventCreateWithFlags(&ev_fork, cudaEventDisableTiming);
        cudaEventCreateWithFlags(&ev_join, cudaEventDisableTiming);
    }

    // ---- fork: CSR build on s2, GEMM1 on main ----
    cudaEventRecord(ev_fork, 0);
    cudaStreamWaitEvent(s2, ev_fork, 0);

    zero_cnt  <<<(M + 255) / 256, 256, 0, s2>>>(M);
    count_deg <<<(E + 511) / 512, 512, 0, s2>>>(ei, E);
    scan_local<<<NBLK, SCAN_B, 0, s2>>>(M);
    scan_apply<<<(M + 255) / 256, 256, 0, s2>>>(M);
    fill_csr  <<<(E + 511) / 512, 512, 0, s2>>>(ei, E);
    cudaEventRecord(ev_join, s2);

    // GEMM1: t1h = fp16(x @ W1), swizzled 1-D grid (4 col-tiles adjacent)
    {
        int nbx = (M + TBM - 1) / TBM;
        int nby = C1 / TBN;   // 4
        gemm_h16<false><<<nbx * nby, 256>>>(x, 512, W1, W1, C1, nby, nby,
                                            t1h, C1, nullptr, M, 512);
    }

    cudaStreamWaitEvent(0, ev_join, 0);
    gather1<<<(M * 32 + 255) / 256, 256>>>(b1, M);

    // GEMM2: t2h = dinv * (hh @ [W_mu | W_lv]), swizzled
    {
        int nbx = (M + TBM - 1) / TBM;
        gemm_h16<true><<<nbx * 2, 256>>>(hh, C1, W_mu, W_lv, 64, 2, 1,
                                         t2h, C2, dinv, M, C1);
    }
    gather2_head<<<(M * 32 + 255) / 256, 256>>>(b_mu, b_lv, W_c, b_c, eps, out, M);
}